// round 14
// baseline (speedup 1.0000x reference)
#include <cuda_runtime.h>
#include <cuda_bf16.h>
#include <math.h>
#include <stdint.h>

#define NROWS 16384
#define Tt 15
#define EPSg 1e-10f

typedef unsigned long long u64t;

// ---------------- scratch ----------------
__device__ float g_h[NROWS*64];
__device__ float g_q[NROWS*64];
__device__ float g_k[NROWS*64];
__device__ float g_v[NROWS*64];
// PLAIN layout: [row][gate*64+c]; Cb has bih (+bhh for r,z) folded
__device__ float g_Gf [NROWS*192];
__device__ float g_Cbf[NROWS*192];
__device__ float g_Gb [NROWS*192];
__device__ float g_Cbb[NROWS*192];
__device__ float g_lf[NROWS*2*Tt];
__device__ float g_lb[NROWS*2*Tt];
__device__ float g_Wc[64*3*32*4];

__device__ __forceinline__ float sigm(float x){ return 1.0f/(1.0f+__expf(-x)); }
__device__ __forceinline__ float tanh_(float x){ return 2.0f/(1.0f+__expf(-2.0f*x)) - 1.0f; }

__device__ __forceinline__ u64t pk(float x, float y){
    u64t r; asm("mov.b64 %0,{%1,%2};" : "=l"(r) : "f"(x), "f"(y)); return r;
}
__device__ __forceinline__ float2 up(u64t v){
    float2 r; asm("mov.b64 {%0,%1},%2;" : "=f"(r.x), "=f"(r.y) : "l"(v)); return r;
}
__device__ __forceinline__ void fma2(u64t& d, u64t a, u64t b){
    asm("fma.rn.f32x2 %0,%1,%2,%0;" : "+l"(d) : "l"(a), "l"(b));
}
__device__ __forceinline__ int pairpos64(int d, int c){
    return ((d<<5) + (((c>>5)&1)<<4) + (c&15))*2 + ((c>>4)&1);
}
__device__ __forceinline__ uint32_t bfpair(float a, float b){
    __nv_bfloat162 t = __floats2bfloat162_rn(a, b);
    return *(uint32_t*)&t;
}
__device__ __forceinline__ float bfhi(float x){
    return __bfloat162float(__float2bfloat16(x));
}
__device__ __forceinline__ float2 bf2f(uint32_t u){
    __nv_bfloat162 b = *(__nv_bfloat162*)&u;
    return __bfloat1622float2(b);
}
__device__ __forceinline__ void mma16816(float* d, uint32_t a0, uint32_t a1,
                                         uint32_t a2, uint32_t a3,
                                         uint32_t b0, uint32_t b1){
    asm volatile(
      "mma.sync.aligned.m16n8k16.row.col.f32.bf16.bf16.f32 "
      "{%0,%1,%2,%3},{%4,%5,%6,%7},{%8,%9},{%0,%1,%2,%3};"
      : "+f"(d[0]), "+f"(d[1]), "+f"(d[2]), "+f"(d[3])
      : "r"(a0), "r"(a1), "r"(a2), "r"(a3), "r"(b0), "r"(b1));
}

// =====================================================================
// K0: encoder (unchanged)
// =====================================================================
__global__ __launch_bounds__(256)
void k_enc(const float* __restrict__ obs,
           const float* __restrict__ W_enc, const float* __restrict__ b_enc)
{
    extern __shared__ float sm[];
    float* Os = sm;
    float* Wt = sm + 64*68;
    const u64t* Wt64 = (const u64t*)Wt;
    const int tid = threadIdx.x;
    const int rbase = blockIdx.x * 64;
    const int ty = tid >> 4, tx = tid & 15;
    const int r0 = ty * 4;
    int dcol[4];
    #pragma unroll
    for (int k=0;k<4;k++) dcol[k] = tx + ((k>>1)<<5) + ((k&1)<<4);

    for (int idx = tid; idx < 4096; idx += 256) {
        int r = idx >> 6, c = idx & 63;
        Os[r*68+c] = obs[(rbase+r)*64 + c];
        Wt[pairpos64(r, c)] = W_enc[idx];
    }
    __syncthreads();

    u64t acc[4][2];
    #pragma unroll
    for (int i=0;i<4;i++){ acc[i][0]=0ull; acc[i][1]=0ull; }
    for (int dd=0; dd<64; ++dd){
        u64t pa[4];
        #pragma unroll
        for (int i=0;i<4;i++){ float a=Os[(r0+i)*68+dd]; pa[i]=pk(a,a); }
        #pragma unroll
        for (int p=0;p<2;p++){
            u64t w = Wt64[dd*32 + p*16 + tx];
            #pragma unroll
            for (int i=0;i<4;i++) fma2(acc[i][p], pa[i], w);
        }
    }
    #pragma unroll
    for (int i=0;i<4;i++)
        #pragma unroll
        for (int p=0;p<2;p++){
            float2 v = up(acc[i][p]);
            int d0 = dcol[2*p], d1 = dcol[2*p+1];
            g_h[(rbase+r0+i)*64 + d0] = fmaxf(v.x + b_enc[d0], 0.0f);
            g_h[(rbase+r0+i)*64 + d1] = fmaxf(v.y + b_enc[d1], 0.0f);
        }
}

// =====================================================================
// K0b: pack cell weights (unchanged)
// =====================================================================
__global__ __launch_bounds__(256)
void k_packW(const float* __restrict__ Wih_c, const float* __restrict__ Whh_c)
{
    int idx = blockIdx.x * 256 + threadIdx.x;
    if (idx >= 6144) return;
    int dd = idx / 96;
    int rem = idx - dd*96;
    int gate = rem >> 5;
    int c = rem & 31;
    float4 w;
    w.x = Wih_c[(gate*64 + c     )*64 + dd];
    w.y = Wih_c[(gate*64 + c + 32)*64 + dd];
    w.z = Whh_c[(gate*64 + c     )*64 + dd];
    w.w = Whh_c[(gate*64 + c + 32)*64 + dd];
    ((float4*)g_Wc)[idx] = w;
}

// =====================================================================
// K1: projections (unchanged from passing R12)
// =====================================================================
__global__ __launch_bounds__(256)
void k_proj2(const float* __restrict__ Wq, const float* __restrict__ Wk,
             const float* __restrict__ Wv, const float* __restrict__ b_v,
             const float* __restrict__ Wih_f, const float* __restrict__ bih_f,
             const float* __restrict__ Wih_b, const float* __restrict__ bih_b,
             const float* __restrict__ bhh_f, const float* __restrict__ bhh_b)
{
    extern __shared__ float sm[];
    float* Hs = sm;
    float* Wt = sm + 64*68;
    const u64t* Wt64 = (const u64t*)Wt;
    const int tid = threadIdx.x;
    const int rbase = blockIdx.x * 64;
    const int gy = blockIdx.y;
    const int ty = tid >> 4, tx = tid & 15;
    const int r0 = ty * 4;
    int dcol[4];
    #pragma unroll
    for (int k=0;k<4;k++) dcol[k] = tx + ((k>>1)<<5) + ((k&1)<<4);

    for (int idx = tid; idx < 4096; idx += 256) {
        int r = idx >> 6, c = idx & 63;
        Hs[r*68+c] = g_h[(rbase+r)*64 + c];
    }

    for (int j = 0; j < 3; ++j){
        const float* Wsrc=nullptr; const float* bias=nullptr; const float* bhh=nullptr;
        float* dst=nullptr; int mode; int doRelu=0; int gate=j;
        if (gy==0){
            mode=0;
            if (j==0){ Wsrc=Wq; dst=g_q; }
            else if (j==1){ Wsrc=Wk; dst=g_k; }
            else { Wsrc=Wv; dst=g_v; bias=b_v; doRelu=1; }
        } else if (gy==1){ mode=1; Wsrc=Wih_f; dst=g_Cbf; bias=bih_f; bhh=bhh_f; }
        else if   (gy==2){ mode=2; Wsrc=Wih_f; dst=g_Gf; }
        else if   (gy==3){ mode=1; Wsrc=Wih_b; dst=g_Cbb; bias=bih_b; bhh=bhh_b; }
        else              { mode=2; Wsrc=Wih_b; dst=g_Gb; }
        const int colBase = gate*64;

        __syncthreads();
        for (int idx = tid; idx < 4096; idx += 256){
            int hi = idx >> 6, lo = idx & 63;
            if (mode==0) Wt[pairpos64(hi, lo)] = Wsrc[idx];
            else {
                int off = (colBase+hi)*128 + lo + (mode==2 ? 64 : 0);
                Wt[pairpos64(lo, hi)] = Wsrc[off];
            }
        }
        __syncthreads();

        u64t acc[4][2];
        #pragma unroll
        for (int i=0;i<4;i++){ acc[i][0]=0ull; acc[i][1]=0ull; }
        for (int dd=0; dd<64; ++dd){
            u64t pa[4];
            #pragma unroll
            for (int i=0;i<4;i++){ float a=Hs[(r0+i)*68+dd]; pa[i]=pk(a,a); }
            #pragma unroll
            for (int p=0;p<2;p++){
                u64t w = Wt64[dd*32 + p*16 + tx];
                #pragma unroll
                for (int i=0;i<4;i++) fma2(acc[i][p], pa[i], w);
            }
        }

        #pragma unroll
        for (int i=0;i<4;i++)
            #pragma unroll
            for (int p=0;p<2;p++){
                float2 v = up(acc[i][p]);
                #pragma unroll
                for (int h=0;h<2;h++){
                    int d = dcol[2*p+h];
                    float vv = (h ? v.y : v.x);
                    if (mode==0){
                        if (bias) vv += bias[d];
                        if (doRelu) vv = fmaxf(vv, 0.0f);
                        dst[(rbase+r0+i)*64 + d] = vv;
                    } else {
                        if (mode==1){
                            vv += bias[colBase+d];
                            if (gate < 2) vv += bhh[colBase+d];
                        }
                        dst[(rbase+r0+i)*192 + colBase + d] = vv;
                    }
                }
            }
    }
}

// =====================================================================
// K2: GRU via mma.sync m16n8k16 bf16 (3-term split), two-phase schedule.
// grid 512, block 128 (4 warps), 3 CTAs/SM target. Warp owns 16 rows.
// Phase 1: 16 r/z tiles -> 192 independent MMAs -> sigm in place (RZ).
// Phase 2: 8 n tiles -> 96 MMAs -> per-tile epilogue overwrites A frags.
// Logits (tile 24) on new A each step.
// smem: B fragments [split2][kt4][jn25][lane32] u64 = 50KB
// =====================================================================
__global__ __launch_bounds__(128,3)
void k_gru_mma(const float* __restrict__ Whh_f, const float* __restrict__ Whh_b,
               const float* __restrict__ bhh_f, const float* __restrict__ bhh_b,
               const float* __restrict__ W_hard)
{
    extern __shared__ u64t Bsm[];   // 6400 u64
    const int tid = threadIdx.x;
    const int w = tid >> 5, lane = tid & 31;
    const int g = lane >> 2, tg = lane & 3;
    const int fwd = (blockIdx.x < 256);
    const int rbase = (blockIdx.x & 255) * 64;
    const float* Whh = fwd ? Whh_f : Whh_b;
    const float* bhh = fwd ? bhh_f : bhh_b;
    const float* Gg  = fwd ? g_Gf  : g_Gb;
    const float* Cbg = fwd ? g_Cbf : g_Cbb;
    u64t* lout = (u64t*)(fwd ? g_lf : g_lb);
    const int whb = fwd ? 0 : 64;

    // ---- build per-lane B fragments (hi/lo bf16) ----
    for (int idx = tid; idx < 6400; idx += 128){
        int ln = idx & 31, f = idx >> 5;
        int split = f / 100, rem = f - split*100;
        int kt = rem / 25, jn = rem - kt*25;
        int gg = ln >> 2, tt = ln & 3;
        float w0,w1,w2,w3;
        if (jn < 24){
            const float* src = Whh + (8*jn + gg)*64 + 16*kt;
            w0 = src[2*tt]; w1 = src[2*tt+1]; w2 = src[8+2*tt]; w3 = src[9+2*tt];
        } else if (gg < 2){
            int kb = whb + 16*kt;
            w0 = W_hard[(kb+2*tt  )*2 + gg];
            w1 = W_hard[(kb+2*tt+1)*2 + gg];
            w2 = W_hard[(kb+8+2*tt  )*2 + gg];
            w3 = W_hard[(kb+9+2*tt  )*2 + gg];
        } else { w0=w1=w2=w3=0.f; }
        if (split){
            w0 -= bfhi(w0); w1 -= bfhi(w1); w2 -= bfhi(w2); w3 -= bfhi(w3);
        }
        uint32_t b0 = bfpair(w0,w1), b1 = bfpair(w2,w3);
        Bsm[idx] = ((u64t)b1 << 32) | (u64t)b0;
    }
    __syncthreads();

    const int rowbase = rbase + w*16;
    const int rg0 = rowbase + g, rg8 = rg0 + 8;
    const float* cb0p = Cbg + (size_t)rg0*192 + 2*tg;
    const float* cb8p = Cbg + (size_t)rg8*192 + 2*tg;
    const float* Gbase = Gg + (size_t)rowbase*192 + 2*tg;
    const u64t* Bw = Bsm + lane;

    float bnv[8][2];
    #pragma unroll
    for (int j=0;j<8;j++){
        float2 v = *(const float2*)&bhh[128 + 8*j + 2*tg];
        bnv[j][0] = v.x; bnv[j][1] = v.y;
    }

    uint32_t Ahi[4][4], Alo[4][4];
    #pragma unroll
    for (int kt=0;kt<4;kt++)
        #pragma unroll
        for (int x=0;x<4;x++){ Ahi[kt][x]=0u; Alo[kt][x]=0u; }

    #pragma unroll 1
    for (int ti = 0; ti < Tt; ++ti){
        const int t = fwd ? ti : (Tt-1-ti);
        const int jl0 = t + (t >= g);
        const int jl8 = t + (t >= g+8);
        const float* g0p = Gbase + jl0*192;
        const float* g8p = Gbase + jl8*192;

        // ---- Phase 1: r/z tiles (jn 0..15 at Cb/G offset 8*jn) ----
        float RZ[16][4];
        #pragma unroll
        for (int jj=0; jj<16; ++jj){
            float2 c0 = *(const float2*)(cb0p + 8*jj);
            float2 e0 = *(const float2*)(g0p  + 8*jj);
            float2 c8 = *(const float2*)(cb8p + 8*jj);
            float2 e8 = *(const float2*)(g8p  + 8*jj);
            RZ[jj][0] = c0.x + e0.x; RZ[jj][1] = c0.y + e0.y;
            RZ[jj][2] = c8.x + e8.x; RZ[jj][3] = c8.y + e8.y;
        }
        if (ti){
            #pragma unroll
            for (int jn=0; jn<16; ++jn){
                #pragma unroll
                for (int kt=0; kt<4; ++kt){
                    u64t bh = Bw[((    kt)*25 + jn)*32];
                    u64t bl = Bw[((4 + kt)*25 + jn)*32];
                    uint32_t bh0 = (uint32_t)bh, bh1 = (uint32_t)(bh>>32);
                    uint32_t bl0 = (uint32_t)bl, bl1 = (uint32_t)(bl>>32);
                    mma16816(RZ[jn], Ahi[kt][0],Ahi[kt][1],Ahi[kt][2],Ahi[kt][3], bh0,bh1);
                    mma16816(RZ[jn], Alo[kt][0],Alo[kt][1],Alo[kt][2],Alo[kt][3], bh0,bh1);
                    mma16816(RZ[jn], Ahi[kt][0],Ahi[kt][1],Ahi[kt][2],Ahi[kt][3], bl0,bl1);
                }
            }
        }
        #pragma unroll
        for (int jn=0;jn<16;jn++)
            #pragma unroll
            for (int x=0;x<4;x++) RZ[jn][x] = sigm(RZ[jn][x]);

        // ---- Phase 2: n tiles (jn 16..23), then fused epilogue ----
        float Dn[8][4];
        #pragma unroll
        for (int j=0;j<8;j++){
            Dn[j][0]=bnv[j][0]; Dn[j][1]=bnv[j][1];
            Dn[j][2]=bnv[j][0]; Dn[j][3]=bnv[j][1];
        }
        if (ti){
            #pragma unroll
            for (int j=0; j<8; ++j){
                #pragma unroll
                for (int kt=0; kt<4; ++kt){
                    u64t bh = Bw[((    kt)*25 + 16 + j)*32];
                    u64t bl = Bw[((4 + kt)*25 + 16 + j)*32];
                    uint32_t bh0 = (uint32_t)bh, bh1 = (uint32_t)(bh>>32);
                    uint32_t bl0 = (uint32_t)bl, bl1 = (uint32_t)(bl>>32);
                    mma16816(Dn[j], Ahi[kt][0],Ahi[kt][1],Ahi[kt][2],Ahi[kt][3], bh0,bh1);
                    mma16816(Dn[j], Alo[kt][0],Alo[kt][1],Alo[kt][2],Alo[kt][3], bh0,bh1);
                    mma16816(Dn[j], Ahi[kt][0],Ahi[kt][1],Ahi[kt][2],Ahi[kt][3], bl0,bl1);
                }
            }
        }

        // epilogue: overwrite A in place (h_old consumed once per tile)
        #pragma unroll
        for (int j=0;j<8;++j){
            float2 cn0 = *(const float2*)(cb0p + 128 + 8*j);
            float2 en0 = *(const float2*)(g0p  + 128 + 8*j);
            float2 cn8 = *(const float2*)(cb8p + 128 + 8*j);
            float2 en8 = *(const float2*)(g8p  + 128 + 8*j);
            int kt = j >> 1, px = (j & 1) * 2;
            float2 hA = bf2f(Ahi[kt][px]),   lA = bf2f(Alo[kt][px]);
            float2 hB = bf2f(Ahi[kt][px+1]), lB = bf2f(Alo[kt][px+1]);
            float ho0 = hA.x + lA.x, ho1 = hA.y + lA.y;
            float ho2 = hB.x + lB.x, ho3 = hB.y + lB.y;
            float n0 = tanh_(cn0.x + en0.x + RZ[j][0]*Dn[j][0]);
            float n1 = tanh_(cn0.y + en0.y + RZ[j][1]*Dn[j][1]);
            float n2 = tanh_(cn8.x + en8.x + RZ[j][2]*Dn[j][2]);
            float n3 = tanh_(cn8.y + en8.y + RZ[j][3]*Dn[j][3]);
            float z0 = RZ[8+j][0], z1 = RZ[8+j][1], z2 = RZ[8+j][2], z3 = RZ[8+j][3];
            float h0 = (1.f - z0)*n0 + z0*ho0;
            float h1 = (1.f - z1)*n1 + z1*ho1;
            float h2 = (1.f - z2)*n2 + z2*ho2;
            float h3 = (1.f - z3)*n3 + z3*ho3;
            Ahi[kt][px]   = bfpair(h0, h1);
            Alo[kt][px]   = bfpair(h0 - bfhi(h0), h1 - bfhi(h1));
            Ahi[kt][px+1] = bfpair(h2, h3);
            Alo[kt][px+1] = bfpair(h2 - bfhi(h2), h3 - bfhi(h3));
        }

        // ---- logits of h_ti (new A frags) ----
        {
            float Dl[4] = {0.f,0.f,0.f,0.f};
            #pragma unroll
            for (int kt=0; kt<4; ++kt){
                u64t bh = Bw[((  kt)*25 + 24)*32];
                u64t bl = Bw[((4+kt)*25 + 24)*32];
                mma16816(Dl, Ahi[kt][0],Ahi[kt][1],Ahi[kt][2],Ahi[kt][3],
                         (uint32_t)bh, (uint32_t)(bh>>32));
                mma16816(Dl, Alo[kt][0],Alo[kt][1],Alo[kt][2],Alo[kt][3],
                         (uint32_t)bh, (uint32_t)(bh>>32));
                mma16816(Dl, Ahi[kt][0],Ahi[kt][1],Ahi[kt][2],Ahi[kt][3],
                         (uint32_t)bl, (uint32_t)(bl>>32));
            }
            if (tg == 0){
                lout[(size_t)rg0*Tt + t] = pk(Dl[0], Dl[1]);
                lout[(size_t)rg8*Tt + t] = pk(Dl[2], Dl[3]);
            }
        }
    }
}

// =====================================================================
// K3: gumbel + attention + final GRU cell (unchanged from passing R12)
// =====================================================================
__global__ __launch_bounds__(512,2)
void k_attn_cell(const float* __restrict__ hidden,
                 const float* __restrict__ gum,
                 const float* __restrict__ b_hard,
                 const float* __restrict__ bih_c, const float* __restrict__ bhh_c,
                 float* __restrict__ out)
{
    extern __shared__ float sm[];
    float* qs  = sm;
    float* ks_ = qs  + 64*68;
    float* vs  = ks_ + 64*68;
    float* hds = vs  + 64*68;
    float* xs  = hds + 64*68;
    float* hw  = xs  + 64*68;
    float* sc  = hw  + 64*16;
    const int tid = threadIdx.x;
    const int rbase = blockIdx.x * 64;

    for (int idx=tid; idx<1024; idx+=512){
        int r=idx>>4, c4=idx&15;
        ((float4*)qs )[r*17+c4] = ((const float4*)g_q)[(rbase+r)*16+c4];
        ((float4*)ks_)[r*17+c4] = ((const float4*)g_k)[(rbase+r)*16+c4];
        ((float4*)vs )[r*17+c4] = ((const float4*)g_v)[(rbase+r)*16+c4];
        ((float4*)hds)[r*17+c4] = ((const float4*)hidden)[(rbase+r)*16+c4];
    }
    {
        const float bh0 = b_hard[0], bh1 = b_hard[1];
        for (int idx=tid; idx<64*Tt; idx+=512){
            int r=idx/Tt, t=idx-r*Tt;
            int row = rbase + r;
            float L0 = g_lf[row*(2*Tt)+2*t]   + g_lb[row*(2*Tt)+2*t]   + bh0;
            float L1 = g_lf[row*(2*Tt)+2*t+1] + g_lb[row*(2*Tt)+2*t+1] + bh1;
            int gi = (row*Tt + t)*2;
            float u0 = gum[gi], u1 = gum[gi+1];
            float gg0 = -logf(-logf(u0+EPSg)+EPSg);
            float gg1 = -logf(-logf(u1+EPSg)+EPSg);
            float dlt = ((L1+gg1)-(L0+gg0)) * 100.0f;
            hw[r*16+t] = 1.0f/(1.0f+__expf(-dlt));
        }
    }
    __syncthreads();

    {
        int rp = tid>>3, qq = tid&7;
        #pragma unroll
        for (int s2=0; s2<2; ++s2){
            int t = qq + 8*s2;
            if (t < Tt){
                int ii = rp & 15;
                int jl = (rp & 48) + t + (t>=ii ? 1 : 0);
                float dot=0.f;
                #pragma unroll 8
                for (int d=0; d<64; ++d) dot += qs[rp*68+d]*ks_[jl*68+d];
                sc[rp*16+t] = dot*0.125f;
            }
        }
    }
    __syncthreads();
    if (tid < 64){
        int r=tid;
        float m=-1e30f;
        #pragma unroll
        for (int t=0;t<Tt;t++) m = fmaxf(m, sc[r*16+t]);
        float e[Tt]; float ssum=0.f;
        #pragma unroll
        for (int t=0;t<Tt;t++){ e[t]=__expf(sc[r*16+t]-m); ssum+=e[t]; }
        float inv = 1.0f/ssum;
        #pragma unroll
        for (int t=0;t<Tt;t++) sc[r*16+t] = e[t]*inv*hw[r*16+t];
    }
    __syncthreads();
    for (int idx=tid; idx<4096; idx+=512){
        int r=idx>>6, d=idx&63;
        int ii = r & 15, rb2 = r & 48;
        float x=0.f;
        #pragma unroll
        for (int t=0;t<Tt;t++){
            int jl = rb2 + t + (t>=ii ? 1 : 0);
            x += vs[jl*68+d]*sc[r*16+t];
        }
        xs[r*68+d]=x;
    }
    __syncthreads();

    const int wid = tid >> 5, lane = tid & 31;
    const int r0 = wid * 4;
    const float4* Wc4 = (const float4*)g_Wc;

    float2 aR[4], aZ[4], aI[4], aH[4];
    #pragma unroll
    for (int i=0;i<4;i++){
        aR[i]=make_float2(0.f,0.f); aZ[i]=make_float2(0.f,0.f);
        aI[i]=make_float2(0.f,0.f); aH[i]=make_float2(0.f,0.f);
    }
    #pragma unroll 2
    for (int dd=0; dd<64; ++dd){
        float4 w0 = Wc4[(dd*3+0)*32 + lane];
        float4 w1 = Wc4[(dd*3+1)*32 + lane];
        float4 w2 = Wc4[(dd*3+2)*32 + lane];
        #pragma unroll
        for (int i=0;i<4;i++){
            float x = xs [(r0+i)*68 + dd];
            float h = hds[(r0+i)*68 + dd];
            aR[i].x += x*w0.x + h*w0.z;  aR[i].y += x*w0.y + h*w0.w;
            aZ[i].x += x*w1.x + h*w1.z;  aZ[i].y += x*w1.y + h*w1.w;
            aI[i].x += x*w2.x;           aI[i].y += x*w2.y;
            aH[i].x += h*w2.z;           aH[i].y += h*w2.w;
        }
    }
    float brc_lo = bih_c[lane]      + bhh_c[lane];
    float brc_hi = bih_c[lane+32]   + bhh_c[lane+32];
    float bzc_lo = bih_c[64+lane]   + bhh_c[64+lane];
    float bzc_hi = bih_c[96+lane]   + bhh_c[96+lane];
    float bni_lo = bih_c[128+lane],  bni_hi = bih_c[160+lane];
    float bnh_lo = bhh_c[128+lane],  bnh_hi = bhh_c[160+lane];
    #pragma unroll
    for (int i=0;i<4;i++){
        int rl = r0+i;
        float ho_lo = hds[rl*68 + lane];
        float ho_hi = hds[rl*68 + 32 + lane];
        float r_lo = sigm(aR[i].x + brc_lo);
        float r_hi = sigm(aR[i].y + brc_hi);
        float z_lo = sigm(aZ[i].x + bzc_lo);
        float z_hi = sigm(aZ[i].y + bzc_hi);
        float n_lo = tanh_(aI[i].x + bni_lo + r_lo*(aH[i].x + bnh_lo));
        float n_hi = tanh_(aI[i].y + bni_hi + r_hi*(aH[i].y + bnh_hi));
        out[(rbase+rl)*64 + lane]      = (1.0f - z_lo)*n_lo + z_lo*ho_lo;
        out[(rbase+rl)*64 + 32 + lane] = (1.0f - z_hi)*n_hi + z_hi*ho_hi;
    }
}

// =====================================================================
extern "C" void kernel_launch(void* const* d_in, const int* in_sizes, int n_in,
                              void* d_out, int out_size)
{
    (void)in_sizes; (void)n_in; (void)out_size;
    const float* obs    = (const float*)d_in[0];
    const float* hidden = (const float*)d_in[1];
    const float* gum    = (const float*)d_in[2];
    const float* W_enc  = (const float*)d_in[3];
    const float* b_enc  = (const float*)d_in[4];
    const float* Wih_f  = (const float*)d_in[5];
    const float* Whh_f  = (const float*)d_in[6];
    const float* bih_f  = (const float*)d_in[7];
    const float* bhh_f  = (const float*)d_in[8];
    const float* Wih_b  = (const float*)d_in[9];
    const float* Whh_b  = (const float*)d_in[10];
    const float* bih_b  = (const float*)d_in[11];
    const float* bhh_b  = (const float*)d_in[12];
    const float* W_hard = (const float*)d_in[13];
    const float* b_hard = (const float*)d_in[14];
    const float* Wq     = (const float*)d_in[15];
    const float* Wk     = (const float*)d_in[16];
    const float* Wv     = (const float*)d_in[17];
    const float* b_v    = (const float*)d_in[18];
    const float* Wih_c  = (const float*)d_in[19];
    const float* Whh_c  = (const float*)d_in[20];
    const float* bih_c  = (const float*)d_in[21];
    const float* bhh_c  = (const float*)d_in[22];
    float* out = (float*)d_out;

    const int sm0 = (64*68 + 4096) * (int)sizeof(float);      // 33,792 B
    const int sm1 = (64*68 + 4096) * (int)sizeof(float);      // 33,792 B
    const int sm2 = 6400 * (int)sizeof(u64t);                 // 51,200 B
    const int sm4 = (5*64*68 + 2*64*16) * (int)sizeof(float); // 95,232 B

    cudaFuncSetAttribute(k_enc,       cudaFuncAttributeMaxDynamicSharedMemorySize, sm0);
    cudaFuncSetAttribute(k_proj2,     cudaFuncAttributeMaxDynamicSharedMemorySize, sm1);
    cudaFuncSetAttribute(k_gru_mma,   cudaFuncAttributeMaxDynamicSharedMemorySize, sm2);
    cudaFuncSetAttribute(k_attn_cell, cudaFuncAttributeMaxDynamicSharedMemorySize, sm4);

    k_enc<<<256, 256, sm0>>>(obs, W_enc, b_enc);
    k_packW<<<24, 256>>>(Wih_c, Whh_c);
    k_proj2<<<dim3(256,5), 256, sm1>>>(Wq, Wk, Wv, b_v,
                                       Wih_f, bih_f, Wih_b, bih_b,
                                       bhh_f, bhh_b);
    k_gru_mma<<<512, 128, sm2>>>(Whh_f, Whh_b, bhh_f, bhh_b, W_hard);
    k_attn_cell<<<256, 512, sm4>>>(hidden, gum, b_hard, bih_c, bhh_c, out);
}

// round 15
// speedup vs baseline: 1.2803x; 1.2803x over previous
#include <cuda_runtime.h>
#include <cuda_bf16.h>
#include <math.h>
#include <stdint.h>

#define NROWS 16384
#define Tt 15
#define EPSg 1e-10f

typedef unsigned long long u64t;

// ---------------- scratch ----------------
__device__ float g_h[NROWS*64];
__device__ float g_q[NROWS*64];
__device__ float g_k[NROWS*64];
__device__ float g_v[NROWS*64];
// PLAIN layout: [row][gate*64+c]; Cb has bih (+bhh for r,z) folded
__device__ float g_Gf [NROWS*192];
__device__ float g_Cbf[NROWS*192];
__device__ float g_Gb [NROWS*192];
__device__ float g_Cbb[NROWS*192];
__device__ float g_lf[NROWS*2*Tt];
__device__ float g_lb[NROWS*2*Tt];
__device__ float g_Wc[64*3*32*4];
// projection B fragments [split2][kt4][jn120][lane32] + folded bias
__device__ u64t  g_Wp[2*4*120*32];
__device__ float g_Bb[960];

__device__ __forceinline__ float sigm(float x){ return 1.0f/(1.0f+__expf(-x)); }
__device__ __forceinline__ float tanh_(float x){ return 2.0f/(1.0f+__expf(-2.0f*x)) - 1.0f; }

__device__ __forceinline__ u64t pk(float x, float y){
    u64t r; asm("mov.b64 %0,{%1,%2};" : "=l"(r) : "f"(x), "f"(y)); return r;
}
__device__ __forceinline__ float2 up(u64t v){
    float2 r; asm("mov.b64 {%0,%1},%2;" : "=f"(r.x), "=f"(r.y) : "l"(v)); return r;
}
__device__ __forceinline__ void fma2(u64t& d, u64t a, u64t b){
    asm("fma.rn.f32x2 %0,%1,%2,%0;" : "+l"(d) : "l"(a), "l"(b));
}
__device__ __forceinline__ int pairpos64(int d, int c){
    return ((d<<5) + (((c>>5)&1)<<4) + (c&15))*2 + ((c>>4)&1);
}
__device__ __forceinline__ uint32_t bfpair(float a, float b){
    __nv_bfloat162 t = __floats2bfloat162_rn(a, b);
    return *(uint32_t*)&t;
}
__device__ __forceinline__ float bfhi(float x){
    return __bfloat162float(__float2bfloat16(x));
}
__device__ __forceinline__ float2 bf2f(uint32_t u){
    __nv_bfloat162 b = *(__nv_bfloat162*)&u;
    return __bfloat1622float2(b);
}
__device__ __forceinline__ void mma16816(float* d, uint32_t a0, uint32_t a1,
                                         uint32_t a2, uint32_t a3,
                                         uint32_t b0, uint32_t b1){
    asm volatile(
      "mma.sync.aligned.m16n8k16.row.col.f32.bf16.bf16.f32 "
      "{%0,%1,%2,%3},{%4,%5,%6,%7},{%8,%9},{%0,%1,%2,%3};"
      : "+f"(d[0]), "+f"(d[1]), "+f"(d[2]), "+f"(d[3])
      : "r"(a0), "r"(a1), "r"(a2), "r"(a3), "r"(b0), "r"(b1));
}

// =====================================================================
// K0: encoder (unchanged)
// =====================================================================
__global__ __launch_bounds__(256)
void k_enc(const float* __restrict__ obs,
           const float* __restrict__ W_enc, const float* __restrict__ b_enc)
{
    extern __shared__ float sm[];
    float* Os = sm;
    float* Wt = sm + 64*68;
    const u64t* Wt64 = (const u64t*)Wt;
    const int tid = threadIdx.x;
    const int rbase = blockIdx.x * 64;
    const int ty = tid >> 4, tx = tid & 15;
    const int r0 = ty * 4;
    int dcol[4];
    #pragma unroll
    for (int k=0;k<4;k++) dcol[k] = tx + ((k>>1)<<5) + ((k&1)<<4);

    for (int idx = tid; idx < 4096; idx += 256) {
        int r = idx >> 6, c = idx & 63;
        Os[r*68+c] = obs[(rbase+r)*64 + c];
        Wt[pairpos64(r, c)] = W_enc[idx];
    }
    __syncthreads();

    u64t acc[4][2];
    #pragma unroll
    for (int i=0;i<4;i++){ acc[i][0]=0ull; acc[i][1]=0ull; }
    for (int dd=0; dd<64; ++dd){
        u64t pa[4];
        #pragma unroll
        for (int i=0;i<4;i++){ float a=Os[(r0+i)*68+dd]; pa[i]=pk(a,a); }
        #pragma unroll
        for (int p=0;p<2;p++){
            u64t w = Wt64[dd*32 + p*16 + tx];
            #pragma unroll
            for (int i=0;i<4;i++) fma2(acc[i][p], pa[i], w);
        }
    }
    #pragma unroll
    for (int i=0;i<4;i++)
        #pragma unroll
        for (int p=0;p<2;p++){
            float2 v = up(acc[i][p]);
            int d0 = dcol[2*p], d1 = dcol[2*p+1];
            g_h[(rbase+r0+i)*64 + d0] = fmaxf(v.x + b_enc[d0], 0.0f);
            g_h[(rbase+r0+i)*64 + d1] = fmaxf(v.y + b_enc[d1], 0.0f);
        }
}

// =====================================================================
// K0b: pack cell weights (unchanged)
// =====================================================================
__global__ __launch_bounds__(256)
void k_packW(const float* __restrict__ Wih_c, const float* __restrict__ Whh_c)
{
    int idx = blockIdx.x * 256 + threadIdx.x;
    if (idx >= 6144) return;
    int dd = idx / 96;
    int rem = idx - dd*96;
    int gate = rem >> 5;
    int c = rem & 31;
    float4 w;
    w.x = Wih_c[(gate*64 + c     )*64 + dd];
    w.y = Wih_c[(gate*64 + c + 32)*64 + dd];
    w.z = Whh_c[(gate*64 + c     )*64 + dd];
    w.w = Whh_c[(gate*64 + c + 32)*64 + dd];
    ((float4*)g_Wc)[idx] = w;
}

// =====================================================================
// K0c: pack projection weights into per-lane B fragments + folded bias.
// Wall cols m: 0..63 q | 64..127 k | 128..191 v | 192..383 Cbf |
//              384..575 Gf | 576..767 Cbb | 768..959 Gb
// frag: g_Wp[((split*4+kt)*120+jn)*32+lane] =
//   ( W^T[k0][m],W^T[k0+1][m] | W^T[k2][m],W^T[k2+1][m] ) as bf16x2 pair,
//   m = 8*jn + (lane>>2), k0 = 16kt+2tt, k2 = k0+8, tt = lane&3.
// =====================================================================
__device__ __forceinline__ float projW(int k, int m,
    const float* Wq, const float* Wk, const float* Wv,
    const float* Wih_f, const float* Wih_b)
{
    if (m < 192){
        const float* W = (m<64) ? Wq : (m<128 ? Wk : Wv);
        return W[k*64 + (m & 63)];
    }
    if (m < 384) return Wih_f[(m-192)*128 + k];
    if (m < 576) return Wih_f[(m-384)*128 + 64 + k];
    if (m < 768) return Wih_b[(m-576)*128 + k];
    return Wih_b[(m-768)*128 + 64 + k];
}

__global__ __launch_bounds__(256)
void k_packP(const float* __restrict__ Wq, const float* __restrict__ Wk,
             const float* __restrict__ Wv, const float* __restrict__ b_v,
             const float* __restrict__ Wih_f, const float* __restrict__ Wih_b,
             const float* __restrict__ bih_f, const float* __restrict__ bhh_f,
             const float* __restrict__ bih_b, const float* __restrict__ bhh_b)
{
    int idx = blockIdx.x * 256 + threadIdx.x;   // 30720 frag slots
    if (idx < 30720){
        int lane = idx & 31, f = idx >> 5;
        int jn = f % 120, kt = (f/120) & 3, split = f/480;
        int gg = lane >> 2, tt = lane & 3;
        int m = 8*jn + gg;
        int k0 = 16*kt + 2*tt;
        float w0 = projW(k0,   m, Wq,Wk,Wv,Wih_f,Wih_b);
        float w1 = projW(k0+1, m, Wq,Wk,Wv,Wih_f,Wih_b);
        float w2 = projW(k0+8, m, Wq,Wk,Wv,Wih_f,Wih_b);
        float w3 = projW(k0+9, m, Wq,Wk,Wv,Wih_f,Wih_b);
        if (split){
            w0 -= bfhi(w0); w1 -= bfhi(w1); w2 -= bfhi(w2); w3 -= bfhi(w3);
        }
        g_Wp[idx] = ((u64t)bfpair(w2,w3) << 32) | (u64t)bfpair(w0,w1);
    }
    if (idx < 960){
        int m = idx;
        float b = 0.f;
        if (m >= 128 && m < 192) b = b_v[m-128];
        else if (m >= 192 && m < 384){
            int ml = m-192; b = bih_f[ml] + (ml < 128 ? bhh_f[ml] : 0.f);
        } else if (m >= 576 && m < 768){
            int ml = m-576; b = bih_b[ml] + (ml < 128 ? bhh_b[ml] : 0.f);
        }
        g_Bb[m] = b;
    }
}

// =====================================================================
// K1: all projections as one bf16-split tensor-core GEMM.
// grid 256 x 128 thr. Warp owns 16 rows; 120 n-tiles of 8 cols.
// =====================================================================
__global__ __launch_bounds__(128)
void k_proj_mma()
{
    const int tid = threadIdx.x;
    const int w = tid >> 5, lane = tid & 31;
    const int g = lane >> 2, tg = lane & 3;
    const int rowbase = blockIdx.x * 64 + w*16;
    const int rg0 = rowbase + g, rg8 = rg0 + 8;

    // A fragments from h_enc (bf16 hi/lo split)
    uint32_t Ahi[4][4], Alo[4][4];
    #pragma unroll
    for (int kt=0; kt<4; ++kt){
        float2 x0 = *(const float2*)&g_h[(size_t)rg0*64 + 16*kt + 2*tg];
        float2 x1 = *(const float2*)&g_h[(size_t)rg8*64 + 16*kt + 2*tg];
        float2 x2 = *(const float2*)&g_h[(size_t)rg0*64 + 16*kt + 8 + 2*tg];
        float2 x3 = *(const float2*)&g_h[(size_t)rg8*64 + 16*kt + 8 + 2*tg];
        Ahi[kt][0] = bfpair(x0.x, x0.y);
        Alo[kt][0] = bfpair(x0.x - bfhi(x0.x), x0.y - bfhi(x0.y));
        Ahi[kt][1] = bfpair(x1.x, x1.y);
        Alo[kt][1] = bfpair(x1.x - bfhi(x1.x), x1.y - bfhi(x1.y));
        Ahi[kt][2] = bfpair(x2.x, x2.y);
        Alo[kt][2] = bfpair(x2.x - bfhi(x2.x), x2.y - bfhi(x2.y));
        Ahi[kt][3] = bfpair(x3.x, x3.y);
        Alo[kt][3] = bfpair(x3.x - bfhi(x3.x), x3.y - bfhi(x3.y));
    }

    const u64t* Wp = g_Wp + lane;

    #pragma unroll 4
    for (int jn = 0; jn < 120; ++jn){
        float D[4] = {0.f, 0.f, 0.f, 0.f};
        #pragma unroll
        for (int kt=0; kt<4; ++kt){
            u64t bh = Wp[((    kt)*120 + jn)*32];
            u64t bl = Wp[((4 + kt)*120 + jn)*32];
            uint32_t bh0 = (uint32_t)bh, bh1 = (uint32_t)(bh>>32);
            uint32_t bl0 = (uint32_t)bl, bl1 = (uint32_t)(bl>>32);
            mma16816(D, Ahi[kt][0],Ahi[kt][1],Ahi[kt][2],Ahi[kt][3], bh0,bh1);
            mma16816(D, Alo[kt][0],Alo[kt][1],Alo[kt][2],Alo[kt][3], bh0,bh1);
            mma16816(D, Ahi[kt][0],Ahi[kt][1],Ahi[kt][2],Ahi[kt][3], bl0,bl1);
        }
        float2 bb = *(const float2*)&g_Bb[8*jn + 2*tg];
        D[0] += bb.x; D[1] += bb.y; D[2] += bb.x; D[3] += bb.y;
        if (jn >= 16 && jn < 24){
            D[0]=fmaxf(D[0],0.f); D[1]=fmaxf(D[1],0.f);
            D[2]=fmaxf(D[2],0.f); D[3]=fmaxf(D[3],0.f);
        }
        float* dst; int stride, col0;
        if (jn < 8)        { dst = g_q;   stride = 64;  col0 = 8*jn; }
        else if (jn < 16)  { dst = g_k;   stride = 64;  col0 = 8*jn - 64; }
        else if (jn < 24)  { dst = g_v;   stride = 64;  col0 = 8*jn - 128; }
        else {
            int s2 = (jn - 24) / 24;
            col0 = 8*((jn - 24) % 24);
            dst = (s2==0) ? g_Cbf : (s2==1) ? g_Gf : (s2==2) ? g_Cbb : g_Gb;
            stride = 192;
        }
        *(float2*)&dst[(size_t)rg0*stride + col0 + 2*tg] = make_float2(D[0], D[1]);
        *(float2*)&dst[(size_t)rg8*stride + col0 + 2*tg] = make_float2(D[2], D[3]);
    }
}

// =====================================================================
// K2: GRU via mma.sync m16n8k16 bf16 (3-term split) — EXACT R12 version.
// grid 512, block 128 (4 warps), 2 CTAs/SM. Warp owns 16 rows.
// =====================================================================
__global__ __launch_bounds__(128,2)
void k_gru_mma(const float* __restrict__ Whh_f, const float* __restrict__ Whh_b,
               const float* __restrict__ bhh_f, const float* __restrict__ bhh_b,
               const float* __restrict__ W_hard)
{
    extern __shared__ u64t Bsm[];   // 6400 u64
    const int tid = threadIdx.x;
    const int w = tid >> 5, lane = tid & 31;
    const int g = lane >> 2, tg = lane & 3;
    const int fwd = (blockIdx.x < 256);
    const int rbase = (blockIdx.x & 255) * 64;
    const float* Whh = fwd ? Whh_f : Whh_b;
    const float* bhh = fwd ? bhh_f : bhh_b;
    const float* Gg  = fwd ? g_Gf  : g_Gb;
    const float* Cbg = fwd ? g_Cbf : g_Cbb;
    u64t* lout = (u64t*)(fwd ? g_lf : g_lb);
    const int whb = fwd ? 0 : 64;

    for (int idx = tid; idx < 6400; idx += 128){
        int ln = idx & 31, f = idx >> 5;
        int split = f / 100, rem = f - split*100;
        int kt = rem / 25, jn = rem - kt*25;
        int gg = ln >> 2, tt = ln & 3;
        float w0,w1,w2,w3;
        if (jn < 24){
            const float* src = Whh + (8*jn + gg)*64 + 16*kt;
            w0 = src[2*tt]; w1 = src[2*tt+1]; w2 = src[8+2*tt]; w3 = src[9+2*tt];
        } else if (gg < 2){
            int kb = whb + 16*kt;
            w0 = W_hard[(kb+2*tt  )*2 + gg];
            w1 = W_hard[(kb+2*tt+1)*2 + gg];
            w2 = W_hard[(kb+8+2*tt  )*2 + gg];
            w3 = W_hard[(kb+9+2*tt  )*2 + gg];
        } else { w0=w1=w2=w3=0.f; }
        if (split){
            w0 -= bfhi(w0); w1 -= bfhi(w1); w2 -= bfhi(w2); w3 -= bfhi(w3);
        }
        uint32_t b0 = bfpair(w0,w1), b1 = bfpair(w2,w3);
        Bsm[idx] = ((u64t)b1 << 32) | (u64t)b0;
    }
    __syncthreads();

    const int rowbase = rbase + w*16;
    const int rg0 = rowbase + g, rg8 = rg0 + 8;
    const float* cb0p = Cbg + (size_t)rg0*192 + 2*tg;
    const float* cb8p = Cbg + (size_t)rg8*192 + 2*tg;
    const float* Gbase = Gg + (size_t)rowbase*192 + 2*tg;
    const u64t* Bw = Bsm + lane;

    float bnv[8][2];
    #pragma unroll
    for (int j=0;j<8;j++){
        float2 v = *(const float2*)&bhh[128 + 8*j + 2*tg];
        bnv[j][0] = v.x; bnv[j][1] = v.y;
    }

    float D[25][4];
    uint32_t Ahi[4][4], Alo[4][4];
    #pragma unroll
    for (int kt=0;kt<4;kt++)
        #pragma unroll
        for (int x=0;x<4;x++){ Ahi[kt][x]=0u; Alo[kt][x]=0u; }

    #pragma unroll 1
    for (int ti = 0; ti < Tt; ++ti){
        const int t = fwd ? ti : (Tt-1-ti);
        const int jl0 = t + (t >= g);
        const int jl8 = t + (t >= g+8);
        const float* g0p = Gbase + jl0*192;
        const float* g8p = Gbase + jl8*192;

        #pragma unroll
        for (int jj=0; jj<16; ++jj){
            float2 c0 = *(const float2*)(cb0p + 8*jj);
            float2 e0 = *(const float2*)(g0p  + 8*jj);
            float2 c8 = *(const float2*)(cb8p + 8*jj);
            float2 e8 = *(const float2*)(g8p  + 8*jj);
            D[jj][0] = c0.x + e0.x; D[jj][1] = c0.y + e0.y;
            D[jj][2] = c8.x + e8.x; D[jj][3] = c8.y + e8.y;
        }
        #pragma unroll
        for (int j=0;j<8;j++){
            D[16+j][0] = bnv[j][0]; D[16+j][1] = bnv[j][1];
            D[16+j][2] = bnv[j][0]; D[16+j][3] = bnv[j][1];
        }
        D[24][0]=0.f; D[24][1]=0.f; D[24][2]=0.f; D[24][3]=0.f;

        if (ti){
            #pragma unroll
            for (int jn=0; jn<25; ++jn){
                #pragma unroll
                for (int kt=0; kt<4; ++kt){
                    u64t bh = Bw[((    kt)*25 + jn)*32];
                    u64t bl = Bw[((4 + kt)*25 + jn)*32];
                    uint32_t bh0 = (uint32_t)bh, bh1 = (uint32_t)(bh>>32);
                    uint32_t bl0 = (uint32_t)bl, bl1 = (uint32_t)(bl>>32);
                    mma16816(D[jn], Ahi[kt][0],Ahi[kt][1],Ahi[kt][2],Ahi[kt][3], bh0,bh1);
                    mma16816(D[jn], Alo[kt][0],Alo[kt][1],Alo[kt][2],Alo[kt][3], bh0,bh1);
                    mma16816(D[jn], Ahi[kt][0],Ahi[kt][1],Ahi[kt][2],Ahi[kt][3], bl0,bl1);
                }
            }
            if (tg == 0){
                int tp = fwd ? (ti-1) : (Tt-ti);
                lout[(size_t)rg0*Tt + tp] = pk(D[24][0], D[24][1]);
                lout[(size_t)rg8*Tt + tp] = pk(D[24][2], D[24][3]);
            }
        }

        #pragma unroll
        for (int j=0;j<8;++j){
            float2 cn0 = *(const float2*)(cb0p + 128 + 8*j);
            float2 en0 = *(const float2*)(g0p  + 128 + 8*j);
            float2 cn8 = *(const float2*)(cb8p + 128 + 8*j);
            float2 en8 = *(const float2*)(g8p  + 128 + 8*j);
            int kt = j >> 1, px = (j & 1) * 2;
            float2 hA = bf2f(Ahi[kt][px]),   lA = bf2f(Alo[kt][px]);
            float2 hB = bf2f(Ahi[kt][px+1]), lB = bf2f(Alo[kt][px+1]);
            float ho0 = hA.x + lA.x, ho1 = hA.y + lA.y;
            float ho2 = hB.x + lB.x, ho3 = hB.y + lB.y;
            float r0 = sigm(D[j][0]),  r1 = sigm(D[j][1]);
            float r2 = sigm(D[j][2]),  r3 = sigm(D[j][3]);
            float z0 = sigm(D[j+8][0]), z1 = sigm(D[j+8][1]);
            float z2 = sigm(D[j+8][2]), z3 = sigm(D[j+8][3]);
            float n0 = tanh_(cn0.x + en0.x + r0*D[j+16][0]);
            float n1 = tanh_(cn0.y + en0.y + r1*D[j+16][1]);
            float n2 = tanh_(cn8.x + en8.x + r2*D[j+16][2]);
            float n3 = tanh_(cn8.y + en8.y + r3*D[j+16][3]);
            float h0 = (1.f - z0)*n0 + z0*ho0;
            float h1 = (1.f - z1)*n1 + z1*ho1;
            float h2 = (1.f - z2)*n2 + z2*ho2;
            float h3 = (1.f - z3)*n3 + z3*ho3;
            Ahi[kt][px]   = bfpair(h0, h1);
            Alo[kt][px]   = bfpair(h0 - bfhi(h0), h1 - bfhi(h1));
            Ahi[kt][px+1] = bfpair(h2, h3);
            Alo[kt][px+1] = bfpair(h2 - bfhi(h2), h3 - bfhi(h3));
        }
    }

    {
        float dl[4] = {0.f,0.f,0.f,0.f};
        #pragma unroll
        for (int kt=0; kt<4; ++kt){
            u64t bh = Bw[((    kt)*25 + 24)*32];
            u64t bl = Bw[((4 + kt)*25 + 24)*32];
            uint32_t bh0 = (uint32_t)bh, bh1 = (uint32_t)(bh>>32);
            uint32_t bl0 = (uint32_t)bl, bl1 = (uint32_t)(bl>>32);
            mma16816(dl, Ahi[kt][0],Ahi[kt][1],Ahi[kt][2],Ahi[kt][3], bh0,bh1);
            mma16816(dl, Alo[kt][0],Alo[kt][1],Alo[kt][2],Alo[kt][3], bh0,bh1);
            mma16816(dl, Ahi[kt][0],Ahi[kt][1],Ahi[kt][2],Ahi[kt][3], bl0,bl1);
        }
        if (tg == 0){
            int tp = fwd ? (Tt-1) : 0;
            lout[(size_t)rg0*Tt + tp] = pk(dl[0], dl[1]);
            lout[(size_t)rg8*Tt + tp] = pk(dl[2], dl[3]);
        }
    }
}

// =====================================================================
// K3: gumbel + attention + final GRU cell (unchanged from passing R12)
// =====================================================================
__global__ __launch_bounds__(512,2)
void k_attn_cell(const float* __restrict__ hidden,
                 const float* __restrict__ gum,
                 const float* __restrict__ b_hard,
                 const float* __restrict__ bih_c, const float* __restrict__ bhh_c,
                 float* __restrict__ out)
{
    extern __shared__ float sm[];
    float* qs  = sm;
    float* ks_ = qs  + 64*68;
    float* vs  = ks_ + 64*68;
    float* hds = vs  + 64*68;
    float* xs  = hds + 64*68;
    float* hw  = xs  + 64*68;
    float* sc  = hw  + 64*16;
    const int tid = threadIdx.x;
    const int rbase = blockIdx.x * 64;

    for (int idx=tid; idx<1024; idx+=512){
        int r=idx>>4, c4=idx&15;
        ((float4*)qs )[r*17+c4] = ((const float4*)g_q)[(rbase+r)*16+c4];
        ((float4*)ks_)[r*17+c4] = ((const float4*)g_k)[(rbase+r)*16+c4];
        ((float4*)vs )[r*17+c4] = ((const float4*)g_v)[(rbase+r)*16+c4];
        ((float4*)hds)[r*17+c4] = ((const float4*)hidden)[(rbase+r)*16+c4];
    }
    {
        const float bh0 = b_hard[0], bh1 = b_hard[1];
        for (int idx=tid; idx<64*Tt; idx+=512){
            int r=idx/Tt, t=idx-r*Tt;
            int row = rbase + r;
            float L0 = g_lf[row*(2*Tt)+2*t]   + g_lb[row*(2*Tt)+2*t]   + bh0;
            float L1 = g_lf[row*(2*Tt)+2*t+1] + g_lb[row*(2*Tt)+2*t+1] + bh1;
            int gi = (row*Tt + t)*2;
            float u0 = gum[gi], u1 = gum[gi+1];
            float gg0 = -logf(-logf(u0+EPSg)+EPSg);
            float gg1 = -logf(-logf(u1+EPSg)+EPSg);
            float dlt = ((L1+gg1)-(L0+gg0)) * 100.0f;
            hw[r*16+t] = 1.0f/(1.0f+__expf(-dlt));
        }
    }
    __syncthreads();

    {
        int rp = tid>>3, qq = tid&7;
        #pragma unroll
        for (int s2=0; s2<2; ++s2){
            int t = qq + 8*s2;
            if (t < Tt){
                int ii = rp & 15;
                int jl = (rp & 48) + t + (t>=ii ? 1 : 0);
                float dot=0.f;
                #pragma unroll 8
                for (int d=0; d<64; ++d) dot += qs[rp*68+d]*ks_[jl*68+d];
                sc[rp*16+t] = dot*0.125f;
            }
        }
    }
    __syncthreads();
    if (tid < 64){
        int r=tid;
        float m=-1e30f;
        #pragma unroll
        for (int t=0;t<Tt;t++) m = fmaxf(m, sc[r*16+t]);
        float e[Tt]; float ssum=0.f;
        #pragma unroll
        for (int t=0;t<Tt;t++){ e[t]=__expf(sc[r*16+t]-m); ssum+=e[t]; }
        float inv = 1.0f/ssum;
        #pragma unroll
        for (int t=0;t<Tt;t++) sc[r*16+t] = e[t]*inv*hw[r*16+t];
    }
    __syncthreads();
    for (int idx=tid; idx<4096; idx+=512){
        int r=idx>>6, d=idx&63;
        int ii = r & 15, rb2 = r & 48;
        float x=0.f;
        #pragma unroll
        for (int t=0;t<Tt;t++){
            int jl = rb2 + t + (t>=ii ? 1 : 0);
            x += vs[jl*68+d]*sc[r*16+t];
        }
        xs[r*68+d]=x;
    }
    __syncthreads();

    const int wid = tid >> 5, lane = tid & 31;
    const int r0 = wid * 4;
    const float4* Wc4 = (const float4*)g_Wc;

    float2 aR[4], aZ[4], aI[4], aH[4];
    #pragma unroll
    for (int i=0;i<4;i++){
        aR[i]=make_float2(0.f,0.f); aZ[i]=make_float2(0.f,0.f);
        aI[i]=make_float2(0.f,0.f); aH[i]=make_float2(0.f,0.f);
    }
    #pragma unroll 2
    for (int dd=0; dd<64; ++dd){
        float4 w0 = Wc4[(dd*3+0)*32 + lane];
        float4 w1 = Wc4[(dd*3+1)*32 + lane];
        float4 w2 = Wc4[(dd*3+2)*32 + lane];
        #pragma unroll
        for (int i=0;i<4;i++){
            float x = xs [(r0+i)*68 + dd];
            float h = hds[(r0+i)*68 + dd];
            aR[i].x += x*w0.x + h*w0.z;  aR[i].y += x*w0.y + h*w0.w;
            aZ[i].x += x*w1.x + h*w1.z;  aZ[i].y += x*w1.y + h*w1.w;
            aI[i].x += x*w2.x;           aI[i].y += x*w2.y;
            aH[i].x += h*w2.z;           aH[i].y += h*w2.w;
        }
    }
    float brc_lo = bih_c[lane]      + bhh_c[lane];
    float brc_hi = bih_c[lane+32]   + bhh_c[lane+32];
    float bzc_lo = bih_c[64+lane]   + bhh_c[64+lane];
    float bzc_hi = bih_c[96+lane]   + bhh_c[96+lane];
    float bni_lo = bih_c[128+lane],  bni_hi = bih_c[160+lane];
    float bnh_lo = bhh_c[128+lane],  bnh_hi = bhh_c[160+lane];
    #pragma unroll
    for (int i=0;i<4;i++){
        int rl = r0+i;
        float ho_lo = hds[rl*68 + lane];
        float ho_hi = hds[rl*68 + 32 + lane];
        float r_lo = sigm(aR[i].x + brc_lo);
        float r_hi = sigm(aR[i].y + brc_hi);
        float z_lo = sigm(aZ[i].x + bzc_lo);
        float z_hi = sigm(aZ[i].y + bzc_hi);
        float n_lo = tanh_(aI[i].x + bni_lo + r_lo*(aH[i].x + bnh_lo));
        float n_hi = tanh_(aI[i].y + bni_hi + r_hi*(aH[i].y + bnh_hi));
        out[(rbase+rl)*64 + lane]      = (1.0f - z_lo)*n_lo + z_lo*ho_lo;
        out[(rbase+rl)*64 + 32 + lane] = (1.0f - z_hi)*n_hi + z_hi*ho_hi;
    }
}

// =====================================================================
extern "C" void kernel_launch(void* const* d_in, const int* in_sizes, int n_in,
                              void* d_out, int out_size)
{
    (void)in_sizes; (void)n_in; (void)out_size;
    const float* obs    = (const float*)d_in[0];
    const float* hidden = (const float*)d_in[1];
    const float* gum    = (const float*)d_in[2];
    const float* W_enc  = (const float*)d_in[3];
    const float* b_enc  = (const float*)d_in[4];
    const float* Wih_f  = (const float*)d_in[5];
    const float* Whh_f  = (const float*)d_in[6];
    const float* bih_f  = (const float*)d_in[7];
    const float* bhh_f  = (const float*)d_in[8];
    const float* Wih_b  = (const float*)d_in[9];
    const float* Whh_b  = (const float*)d_in[10];
    const float* bih_b  = (const float*)d_in[11];
    const float* bhh_b  = (const float*)d_in[12];
    const float* W_hard = (const float*)d_in[13];
    const float* b_hard = (const float*)d_in[14];
    const float* Wq     = (const float*)d_in[15];
    const float* Wk     = (const float*)d_in[16];
    const float* Wv     = (const float*)d_in[17];
    const float* b_v    = (const float*)d_in[18];
    const float* Wih_c  = (const float*)d_in[19];
    const float* Whh_c  = (const float*)d_in[20];
    const float* bih_c  = (const float*)d_in[21];
    const float* bhh_c  = (const float*)d_in[22];
    float* out = (float*)d_out;

    const int sm0 = (64*68 + 4096) * (int)sizeof(float);      // 33,792 B
    const int sm2 = 6400 * (int)sizeof(u64t);                 // 51,200 B
    const int sm4 = (5*64*68 + 2*64*16) * (int)sizeof(float); // 95,232 B

    cudaFuncSetAttribute(k_enc,       cudaFuncAttributeMaxDynamicSharedMemorySize, sm0);
    cudaFuncSetAttribute(k_gru_mma,   cudaFuncAttributeMaxDynamicSharedMemorySize, sm2);
    cudaFuncSetAttribute(k_attn_cell, cudaFuncAttributeMaxDynamicSharedMemorySize, sm4);

    k_enc<<<256, 256, sm0>>>(obs, W_enc, b_enc);
    k_packW<<<24, 256>>>(Wih_c, Whh_c);
    k_packP<<<120, 256>>>(Wq, Wk, Wv, b_v, Wih_f, Wih_b,
                          bih_f, bhh_f, bih_b, bhh_b);
    k_proj_mma<<<256, 128>>>();
    k_gru_mma<<<512, 128, sm2>>>(Whh_f, Whh_b, bhh_f, bhh_b, W_hard);
    k_attn_cell<<<256, 512, sm4>>>(hidden, gum, b_hard, bih_c, bhh_c, out);
}

// round 16
// speedup vs baseline: 1.4485x; 1.1314x over previous
#include <cuda_runtime.h>
#include <cuda_bf16.h>
#include <math.h>
#include <stdint.h>

#define NROWS 16384
#define Tt 15
#define EPSg 1e-10f

typedef unsigned long long u64t;

// ---------------- scratch ----------------
__device__ float g_h[NROWS*64];
__device__ float g_q[NROWS*64];
__device__ float g_k[NROWS*64];
__device__ float g_v[NROWS*64];
// PLAIN layout: [row][gate*64+c]; Cb has bih (+bhh for r,z) folded
__device__ float g_Gf [NROWS*192];
__device__ float g_Cbf[NROWS*192];
__device__ float g_Gb [NROWS*192];
__device__ float g_Cbb[NROWS*192];
__device__ float g_lf[NROWS*2*Tt];
__device__ float g_lb[NROWS*2*Tt];
__device__ float g_Wc[64*3*32*4];
// projection B fragments [split2][kt4][jn120][lane32] + folded bias
__device__ u64t  g_Wp[2*4*120*32];
__device__ float g_Bb[960];

__device__ __forceinline__ float sigm(float x){ return 1.0f/(1.0f+__expf(-x)); }
__device__ __forceinline__ float tanh_(float x){ return 2.0f/(1.0f+__expf(-2.0f*x)) - 1.0f; }

__device__ __forceinline__ u64t pk(float x, float y){
    u64t r; asm("mov.b64 %0,{%1,%2};" : "=l"(r) : "f"(x), "f"(y)); return r;
}
__device__ __forceinline__ float2 up(u64t v){
    float2 r; asm("mov.b64 {%0,%1},%2;" : "=f"(r.x), "=f"(r.y) : "l"(v)); return r;
}
__device__ __forceinline__ void fma2(u64t& d, u64t a, u64t b){
    asm("fma.rn.f32x2 %0,%1,%2,%0;" : "+l"(d) : "l"(a), "l"(b));
}
__device__ __forceinline__ int pairpos64(int d, int c){
    return ((d<<5) + (((c>>5)&1)<<4) + (c&15))*2 + ((c>>4)&1);
}
__device__ __forceinline__ uint32_t bfpair(float a, float b){
    __nv_bfloat162 t = __floats2bfloat162_rn(a, b);
    return *(uint32_t*)&t;
}
__device__ __forceinline__ float bfhi(float x){
    return __bfloat162float(__float2bfloat16(x));
}
__device__ __forceinline__ float2 bf2f(uint32_t u){
    __nv_bfloat162 b = *(__nv_bfloat162*)&u;
    return __bfloat1622float2(b);
}
__device__ __forceinline__ void mma16816(float* d, uint32_t a0, uint32_t a1,
                                         uint32_t a2, uint32_t a3,
                                         uint32_t b0, uint32_t b1){
    asm volatile(
      "mma.sync.aligned.m16n8k16.row.col.f32.bf16.bf16.f32 "
      "{%0,%1,%2,%3},{%4,%5,%6,%7},{%8,%9},{%0,%1,%2,%3};"
      : "+f"(d[0]), "+f"(d[1]), "+f"(d[2]), "+f"(d[3])
      : "r"(a0), "r"(a1), "r"(a2), "r"(a3), "r"(b0), "r"(b1));
}

// =====================================================================
// K0: encoder (unchanged)
// =====================================================================
__global__ __launch_bounds__(256)
void k_enc(const float* __restrict__ obs,
           const float* __restrict__ W_enc, const float* __restrict__ b_enc)
{
    extern __shared__ float sm[];
    float* Os = sm;
    float* Wt = sm + 64*68;
    const u64t* Wt64 = (const u64t*)Wt;
    const int tid = threadIdx.x;
    const int rbase = blockIdx.x * 64;
    const int ty = tid >> 4, tx = tid & 15;
    const int r0 = ty * 4;
    int dcol[4];
    #pragma unroll
    for (int k=0;k<4;k++) dcol[k] = tx + ((k>>1)<<5) + ((k&1)<<4);

    for (int idx = tid; idx < 4096; idx += 256) {
        int r = idx >> 6, c = idx & 63;
        Os[r*68+c] = obs[(rbase+r)*64 + c];
        Wt[pairpos64(r, c)] = W_enc[idx];
    }
    __syncthreads();

    u64t acc[4][2];
    #pragma unroll
    for (int i=0;i<4;i++){ acc[i][0]=0ull; acc[i][1]=0ull; }
    for (int dd=0; dd<64; ++dd){
        u64t pa[4];
        #pragma unroll
        for (int i=0;i<4;i++){ float a=Os[(r0+i)*68+dd]; pa[i]=pk(a,a); }
        #pragma unroll
        for (int p=0;p<2;p++){
            u64t w = Wt64[dd*32 + p*16 + tx];
            #pragma unroll
            for (int i=0;i<4;i++) fma2(acc[i][p], pa[i], w);
        }
    }
    #pragma unroll
    for (int i=0;i<4;i++)
        #pragma unroll
        for (int p=0;p<2;p++){
            float2 v = up(acc[i][p]);
            int d0 = dcol[2*p], d1 = dcol[2*p+1];
            g_h[(rbase+r0+i)*64 + d0] = fmaxf(v.x + b_enc[d0], 0.0f);
            g_h[(rbase+r0+i)*64 + d1] = fmaxf(v.y + b_enc[d1], 0.0f);
        }
}

// =====================================================================
// K0b: pack cell weights (unchanged)
// =====================================================================
__global__ __launch_bounds__(256)
void k_packW(const float* __restrict__ Wih_c, const float* __restrict__ Whh_c)
{
    int idx = blockIdx.x * 256 + threadIdx.x;
    if (idx >= 6144) return;
    int dd = idx / 96;
    int rem = idx - dd*96;
    int gate = rem >> 5;
    int c = rem & 31;
    float4 w;
    w.x = Wih_c[(gate*64 + c     )*64 + dd];
    w.y = Wih_c[(gate*64 + c + 32)*64 + dd];
    w.z = Whh_c[(gate*64 + c     )*64 + dd];
    w.w = Whh_c[(gate*64 + c + 32)*64 + dd];
    ((float4*)g_Wc)[idx] = w;
}

// =====================================================================
// K0c: pack projection weights (unchanged from R15)
// =====================================================================
__device__ __forceinline__ float projW(int k, int m,
    const float* Wq, const float* Wk, const float* Wv,
    const float* Wih_f, const float* Wih_b)
{
    if (m < 192){
        const float* W = (m<64) ? Wq : (m<128 ? Wk : Wv);
        return W[k*64 + (m & 63)];
    }
    if (m < 384) return Wih_f[(m-192)*128 + k];
    if (m < 576) return Wih_f[(m-384)*128 + 64 + k];
    if (m < 768) return Wih_b[(m-576)*128 + k];
    return Wih_b[(m-768)*128 + 64 + k];
}

__global__ __launch_bounds__(256)
void k_packP(const float* __restrict__ Wq, const float* __restrict__ Wk,
             const float* __restrict__ Wv, const float* __restrict__ b_v,
             const float* __restrict__ Wih_f, const float* __restrict__ Wih_b,
             const float* __restrict__ bih_f, const float* __restrict__ bhh_f,
             const float* __restrict__ bih_b, const float* __restrict__ bhh_b)
{
    int idx = blockIdx.x * 256 + threadIdx.x;   // 30720 frag slots
    if (idx < 30720){
        int lane = idx & 31, f = idx >> 5;
        int jn = f % 120, kt = (f/120) & 3, split = f/480;
        int gg = lane >> 2, tt = lane & 3;
        int m = 8*jn + gg;
        int k0 = 16*kt + 2*tt;
        float w0 = projW(k0,   m, Wq,Wk,Wv,Wih_f,Wih_b);
        float w1 = projW(k0+1, m, Wq,Wk,Wv,Wih_f,Wih_b);
        float w2 = projW(k0+8, m, Wq,Wk,Wv,Wih_f,Wih_b);
        float w3 = projW(k0+9, m, Wq,Wk,Wv,Wih_f,Wih_b);
        if (split){
            w0 -= bfhi(w0); w1 -= bfhi(w1); w2 -= bfhi(w2); w3 -= bfhi(w3);
        }
        g_Wp[idx] = ((u64t)bfpair(w2,w3) << 32) | (u64t)bfpair(w0,w1);
    }
    if (idx < 960){
        int m = idx;
        float b = 0.f;
        if (m >= 128 && m < 192) b = b_v[m-128];
        else if (m >= 192 && m < 384){
            int ml = m-192; b = bih_f[ml] + (ml < 128 ? bhh_f[ml] : 0.f);
        } else if (m >= 576 && m < 768){
            int ml = m-576; b = bih_b[ml] + (ml < 128 ? bhh_b[ml] : 0.f);
        }
        g_Bb[m] = b;
    }
}

// =====================================================================
// K1: projections as bf16-split tensor-core GEMM, now grid (256,5):
// blockIdx.y = tile group, 24 n-tiles each -> 1280 blocks (5x occupancy).
// =====================================================================
__global__ __launch_bounds__(128)
void k_proj_mma()
{
    const int tid = threadIdx.x;
    const int w = tid >> 5, lane = tid & 31;
    const int g = lane >> 2, tg = lane & 3;
    const int rowbase = blockIdx.x * 64 + w*16;
    const int rg0 = rowbase + g, rg8 = rg0 + 8;
    const int jn0 = blockIdx.y * 24;

    // A fragments from h_enc (bf16 hi/lo split)
    uint32_t Ahi[4][4], Alo[4][4];
    #pragma unroll
    for (int kt=0; kt<4; ++kt){
        float2 x0 = *(const float2*)&g_h[(size_t)rg0*64 + 16*kt + 2*tg];
        float2 x1 = *(const float2*)&g_h[(size_t)rg8*64 + 16*kt + 2*tg];
        float2 x2 = *(const float2*)&g_h[(size_t)rg0*64 + 16*kt + 8 + 2*tg];
        float2 x3 = *(const float2*)&g_h[(size_t)rg8*64 + 16*kt + 8 + 2*tg];
        Ahi[kt][0] = bfpair(x0.x, x0.y);
        Alo[kt][0] = bfpair(x0.x - bfhi(x0.x), x0.y - bfhi(x0.y));
        Ahi[kt][1] = bfpair(x1.x, x1.y);
        Alo[kt][1] = bfpair(x1.x - bfhi(x1.x), x1.y - bfhi(x1.y));
        Ahi[kt][2] = bfpair(x2.x, x2.y);
        Alo[kt][2] = bfpair(x2.x - bfhi(x2.x), x2.y - bfhi(x2.y));
        Ahi[kt][3] = bfpair(x3.x, x3.y);
        Alo[kt][3] = bfpair(x3.x - bfhi(x3.x), x3.y - bfhi(x3.y));
    }

    const u64t* Wp = g_Wp + lane;

    #pragma unroll 4
    for (int jj = 0; jj < 24; ++jj){
        const int jn = jn0 + jj;
        float D[4] = {0.f, 0.f, 0.f, 0.f};
        #pragma unroll
        for (int kt=0; kt<4; ++kt){
            u64t bh = Wp[((    kt)*120 + jn)*32];
            u64t bl = Wp[((4 + kt)*120 + jn)*32];
            uint32_t bh0 = (uint32_t)bh, bh1 = (uint32_t)(bh>>32);
            uint32_t bl0 = (uint32_t)bl, bl1 = (uint32_t)(bl>>32);
            mma16816(D, Ahi[kt][0],Ahi[kt][1],Ahi[kt][2],Ahi[kt][3], bh0,bh1);
            mma16816(D, Alo[kt][0],Alo[kt][1],Alo[kt][2],Alo[kt][3], bh0,bh1);
            mma16816(D, Ahi[kt][0],Ahi[kt][1],Ahi[kt][2],Ahi[kt][3], bl0,bl1);
        }
        float2 bb = *(const float2*)&g_Bb[8*jn + 2*tg];
        D[0] += bb.x; D[1] += bb.y; D[2] += bb.x; D[3] += bb.y;
        if (jn >= 16 && jn < 24){
            D[0]=fmaxf(D[0],0.f); D[1]=fmaxf(D[1],0.f);
            D[2]=fmaxf(D[2],0.f); D[3]=fmaxf(D[3],0.f);
        }
        float* dst; int stride, col0;
        if (jn < 8)        { dst = g_q;   stride = 64;  col0 = 8*jn; }
        else if (jn < 16)  { dst = g_k;   stride = 64;  col0 = 8*jn - 64; }
        else if (jn < 24)  { dst = g_v;   stride = 64;  col0 = 8*jn - 128; }
        else {
            int s2 = (jn - 24) / 24;
            col0 = 8*((jn - 24) % 24);
            dst = (s2==0) ? g_Cbf : (s2==1) ? g_Gf : (s2==2) ? g_Cbb : g_Gb;
            stride = 192;
        }
        *(float2*)&dst[(size_t)rg0*stride + col0 + 2*tg] = make_float2(D[0], D[1]);
        *(float2*)&dst[(size_t)rg8*stride + col0 + 2*tg] = make_float2(D[2], D[3]);
    }
}

// =====================================================================
// K2: GRU via mma.sync m16n8k16 bf16 (3-term split) — EXACT R12 version.
// =====================================================================
__global__ __launch_bounds__(128,2)
void k_gru_mma(const float* __restrict__ Whh_f, const float* __restrict__ Whh_b,
               const float* __restrict__ bhh_f, const float* __restrict__ bhh_b,
               const float* __restrict__ W_hard)
{
    extern __shared__ u64t Bsm[];   // 6400 u64
    const int tid = threadIdx.x;
    const int w = tid >> 5, lane = tid & 31;
    const int g = lane >> 2, tg = lane & 3;
    const int fwd = (blockIdx.x < 256);
    const int rbase = (blockIdx.x & 255) * 64;
    const float* Whh = fwd ? Whh_f : Whh_b;
    const float* bhh = fwd ? bhh_f : bhh_b;
    const float* Gg  = fwd ? g_Gf  : g_Gb;
    const float* Cbg = fwd ? g_Cbf : g_Cbb;
    u64t* lout = (u64t*)(fwd ? g_lf : g_lb);
    const int whb = fwd ? 0 : 64;

    for (int idx = tid; idx < 6400; idx += 128){
        int ln = idx & 31, f = idx >> 5;
        int split = f / 100, rem = f - split*100;
        int kt = rem / 25, jn = rem - kt*25;
        int gg = ln >> 2, tt = ln & 3;
        float w0,w1,w2,w3;
        if (jn < 24){
            const float* src = Whh + (8*jn + gg)*64 + 16*kt;
            w0 = src[2*tt]; w1 = src[2*tt+1]; w2 = src[8+2*tt]; w3 = src[9+2*tt];
        } else if (gg < 2){
            int kb = whb + 16*kt;
            w0 = W_hard[(kb+2*tt  )*2 + gg];
            w1 = W_hard[(kb+2*tt+1)*2 + gg];
            w2 = W_hard[(kb+8+2*tt  )*2 + gg];
            w3 = W_hard[(kb+9+2*tt  )*2 + gg];
        } else { w0=w1=w2=w3=0.f; }
        if (split){
            w0 -= bfhi(w0); w1 -= bfhi(w1); w2 -= bfhi(w2); w3 -= bfhi(w3);
        }
        uint32_t b0 = bfpair(w0,w1), b1 = bfpair(w2,w3);
        Bsm[idx] = ((u64t)b1 << 32) | (u64t)b0;
    }
    __syncthreads();

    const int rowbase = rbase + w*16;
    const int rg0 = rowbase + g, rg8 = rg0 + 8;
    const float* cb0p = Cbg + (size_t)rg0*192 + 2*tg;
    const float* cb8p = Cbg + (size_t)rg8*192 + 2*tg;
    const float* Gbase = Gg + (size_t)rowbase*192 + 2*tg;
    const u64t* Bw = Bsm + lane;

    float bnv[8][2];
    #pragma unroll
    for (int j=0;j<8;j++){
        float2 v = *(const float2*)&bhh[128 + 8*j + 2*tg];
        bnv[j][0] = v.x; bnv[j][1] = v.y;
    }

    float D[25][4];
    uint32_t Ahi[4][4], Alo[4][4];
    #pragma unroll
    for (int kt=0;kt<4;kt++)
        #pragma unroll
        for (int x=0;x<4;x++){ Ahi[kt][x]=0u; Alo[kt][x]=0u; }

    #pragma unroll 1
    for (int ti = 0; ti < Tt; ++ti){
        const int t = fwd ? ti : (Tt-1-ti);
        const int jl0 = t + (t >= g);
        const int jl8 = t + (t >= g+8);
        const float* g0p = Gbase + jl0*192;
        const float* g8p = Gbase + jl8*192;

        #pragma unroll
        for (int jj=0; jj<16; ++jj){
            float2 c0 = *(const float2*)(cb0p + 8*jj);
            float2 e0 = *(const float2*)(g0p  + 8*jj);
            float2 c8 = *(const float2*)(cb8p + 8*jj);
            float2 e8 = *(const float2*)(g8p  + 8*jj);
            D[jj][0] = c0.x + e0.x; D[jj][1] = c0.y + e0.y;
            D[jj][2] = c8.x + e8.x; D[jj][3] = c8.y + e8.y;
        }
        #pragma unroll
        for (int j=0;j<8;j++){
            D[16+j][0] = bnv[j][0]; D[16+j][1] = bnv[j][1];
            D[16+j][2] = bnv[j][0]; D[16+j][3] = bnv[j][1];
        }
        D[24][0]=0.f; D[24][1]=0.f; D[24][2]=0.f; D[24][3]=0.f;

        if (ti){
            #pragma unroll
            for (int jn=0; jn<25; ++jn){
                #pragma unroll
                for (int kt=0; kt<4; ++kt){
                    u64t bh = Bw[((    kt)*25 + jn)*32];
                    u64t bl = Bw[((4 + kt)*25 + jn)*32];
                    uint32_t bh0 = (uint32_t)bh, bh1 = (uint32_t)(bh>>32);
                    uint32_t bl0 = (uint32_t)bl, bl1 = (uint32_t)(bl>>32);
                    mma16816(D[jn], Ahi[kt][0],Ahi[kt][1],Ahi[kt][2],Ahi[kt][3], bh0,bh1);
                    mma16816(D[jn], Alo[kt][0],Alo[kt][1],Alo[kt][2],Alo[kt][3], bh0,bh1);
                    mma16816(D[jn], Ahi[kt][0],Ahi[kt][1],Ahi[kt][2],Ahi[kt][3], bl0,bl1);
                }
            }
            if (tg == 0){
                int tp = fwd ? (ti-1) : (Tt-ti);
                lout[(size_t)rg0*Tt + tp] = pk(D[24][0], D[24][1]);
                lout[(size_t)rg8*Tt + tp] = pk(D[24][2], D[24][3]);
            }
        }

        #pragma unroll
        for (int j=0;j<8;++j){
            float2 cn0 = *(const float2*)(cb0p + 128 + 8*j);
            float2 en0 = *(const float2*)(g0p  + 128 + 8*j);
            float2 cn8 = *(const float2*)(cb8p + 128 + 8*j);
            float2 en8 = *(const float2*)(g8p  + 128 + 8*j);
            int kt = j >> 1, px = (j & 1) * 2;
            float2 hA = bf2f(Ahi[kt][px]),   lA = bf2f(Alo[kt][px]);
            float2 hB = bf2f(Ahi[kt][px+1]), lB = bf2f(Alo[kt][px+1]);
            float ho0 = hA.x + lA.x, ho1 = hA.y + lA.y;
            float ho2 = hB.x + lB.x, ho3 = hB.y + lB.y;
            float r0 = sigm(D[j][0]),  r1 = sigm(D[j][1]);
            float r2 = sigm(D[j][2]),  r3 = sigm(D[j][3]);
            float z0 = sigm(D[j+8][0]), z1 = sigm(D[j+8][1]);
            float z2 = sigm(D[j+8][2]), z3 = sigm(D[j+8][3]);
            float n0 = tanh_(cn0.x + en0.x + r0*D[j+16][0]);
            float n1 = tanh_(cn0.y + en0.y + r1*D[j+16][1]);
            float n2 = tanh_(cn8.x + en8.x + r2*D[j+16][2]);
            float n3 = tanh_(cn8.y + en8.y + r3*D[j+16][3]);
            float h0 = (1.f - z0)*n0 + z0*ho0;
            float h1 = (1.f - z1)*n1 + z1*ho1;
            float h2 = (1.f - z2)*n2 + z2*ho2;
            float h3 = (1.f - z3)*n3 + z3*ho3;
            Ahi[kt][px]   = bfpair(h0, h1);
            Alo[kt][px]   = bfpair(h0 - bfhi(h0), h1 - bfhi(h1));
            Ahi[kt][px+1] = bfpair(h2, h3);
            Alo[kt][px+1] = bfpair(h2 - bfhi(h2), h3 - bfhi(h3));
        }
    }

    {
        float dl[4] = {0.f,0.f,0.f,0.f};
        #pragma unroll
        for (int kt=0; kt<4; ++kt){
            u64t bh = Bw[((    kt)*25 + 24)*32];
            u64t bl = Bw[((4 + kt)*25 + 24)*32];
            uint32_t bh0 = (uint32_t)bh, bh1 = (uint32_t)(bh>>32);
            uint32_t bl0 = (uint32_t)bl, bl1 = (uint32_t)(bl>>32);
            mma16816(dl, Ahi[kt][0],Ahi[kt][1],Ahi[kt][2],Ahi[kt][3], bh0,bh1);
            mma16816(dl, Alo[kt][0],Alo[kt][1],Alo[kt][2],Alo[kt][3], bh0,bh1);
            mma16816(dl, Ahi[kt][0],Ahi[kt][1],Ahi[kt][2],Ahi[kt][3], bl0,bl1);
        }
        if (tg == 0){
            int tp = fwd ? (Tt-1) : 0;
            lout[(size_t)rg0*Tt + tp] = pk(dl[0], dl[1]);
            lout[(size_t)rg8*Tt + tp] = pk(dl[2], dl[3]);
        }
    }
}

// =====================================================================
// K3: gumbel + attention + final GRU cell (unchanged)
// =====================================================================
__global__ __launch_bounds__(512,2)
void k_attn_cell(const float* __restrict__ hidden,
                 const float* __restrict__ gum,
                 const float* __restrict__ b_hard,
                 const float* __restrict__ bih_c, const float* __restrict__ bhh_c,
                 float* __restrict__ out)
{
    extern __shared__ float sm[];
    float* qs  = sm;
    float* ks_ = qs  + 64*68;
    float* vs  = ks_ + 64*68;
    float* hds = vs  + 64*68;
    float* xs  = hds + 64*68;
    float* hw  = xs  + 64*68;
    float* sc  = hw  + 64*16;
    const int tid = threadIdx.x;
    const int rbase = blockIdx.x * 64;

    for (int idx=tid; idx<1024; idx+=512){
        int r=idx>>4, c4=idx&15;
        ((float4*)qs )[r*17+c4] = ((const float4*)g_q)[(rbase+r)*16+c4];
        ((float4*)ks_)[r*17+c4] = ((const float4*)g_k)[(rbase+r)*16+c4];
        ((float4*)vs )[r*17+c4] = ((const float4*)g_v)[(rbase+r)*16+c4];
        ((float4*)hds)[r*17+c4] = ((const float4*)hidden)[(rbase+r)*16+c4];
    }
    {
        const float bh0 = b_hard[0], bh1 = b_hard[1];
        for (int idx=tid; idx<64*Tt; idx+=512){
            int r=idx/Tt, t=idx-r*Tt;
            int row = rbase + r;
            float L0 = g_lf[row*(2*Tt)+2*t]   + g_lb[row*(2*Tt)+2*t]   + bh0;
            float L1 = g_lf[row*(2*Tt)+2*t+1] + g_lb[row*(2*Tt)+2*t+1] + bh1;
            int gi = (row*Tt + t)*2;
            float u0 = gum[gi], u1 = gum[gi+1];
            float gg0 = -logf(-logf(u0+EPSg)+EPSg);
            float gg1 = -logf(-logf(u1+EPSg)+EPSg);
            float dlt = ((L1+gg1)-(L0+gg0)) * 100.0f;
            hw[r*16+t] = 1.0f/(1.0f+__expf(-dlt));
        }
    }
    __syncthreads();

    {
        int rp = tid>>3, qq = tid&7;
        #pragma unroll
        for (int s2=0; s2<2; ++s2){
            int t = qq + 8*s2;
            if (t < Tt){
                int ii = rp & 15;
                int jl = (rp & 48) + t + (t>=ii ? 1 : 0);
                float dot=0.f;
                #pragma unroll 8
                for (int d=0; d<64; ++d) dot += qs[rp*68+d]*ks_[jl*68+d];
                sc[rp*16+t] = dot*0.125f;
            }
        }
    }
    __syncthreads();
    if (tid < 64){
        int r=tid;
        float m=-1e30f;
        #pragma unroll
        for (int t=0;t<Tt;t++) m = fmaxf(m, sc[r*16+t]);
        float e[Tt]; float ssum=0.f;
        #pragma unroll
        for (int t=0;t<Tt;t++){ e[t]=__expf(sc[r*16+t]-m); ssum+=e[t]; }
        float inv = 1.0f/ssum;
        #pragma unroll
        for (int t=0;t<Tt;t++) sc[r*16+t] = e[t]*inv*hw[r*16+t];
    }
    __syncthreads();
    for (int idx=tid; idx<4096; idx+=512){
        int r=idx>>6, d=idx&63;
        int ii = r & 15, rb2 = r & 48;
        float x=0.f;
        #pragma unroll
        for (int t=0;t<Tt;t++){
            int jl = rb2 + t + (t>=ii ? 1 : 0);
            x += vs[jl*68+d]*sc[r*16+t];
        }
        xs[r*68+d]=x;
    }
    __syncthreads();

    const int wid = tid >> 5, lane = tid & 31;
    const int r0 = wid * 4;
    const float4* Wc4 = (const float4*)g_Wc;

    float2 aR[4], aZ[4], aI[4], aH[4];
    #pragma unroll
    for (int i=0;i<4;i++){
        aR[i]=make_float2(0.f,0.f); aZ[i]=make_float2(0.f,0.f);
        aI[i]=make_float2(0.f,0.f); aH[i]=make_float2(0.f,0.f);
    }
    #pragma unroll 2
    for (int dd=0; dd<64; ++dd){
        float4 w0 = Wc4[(dd*3+0)*32 + lane];
        float4 w1 = Wc4[(dd*3+1)*32 + lane];
        float4 w2 = Wc4[(dd*3+2)*32 + lane];
        #pragma unroll
        for (int i=0;i<4;i++){
            float x = xs [(r0+i)*68 + dd];
            float h = hds[(r0+i)*68 + dd];
            aR[i].x += x*w0.x + h*w0.z;  aR[i].y += x*w0.y + h*w0.w;
            aZ[i].x += x*w1.x + h*w1.z;  aZ[i].y += x*w1.y + h*w1.w;
            aI[i].x += x*w2.x;           aI[i].y += x*w2.y;
            aH[i].x += h*w2.z;           aH[i].y += h*w2.w;
        }
    }
    float brc_lo = bih_c[lane]      + bhh_c[lane];
    float brc_hi = bih_c[lane+32]   + bhh_c[lane+32];
    float bzc_lo = bih_c[64+lane]   + bhh_c[64+lane];
    float bzc_hi = bih_c[96+lane]   + bhh_c[96+lane];
    float bni_lo = bih_c[128+lane],  bni_hi = bih_c[160+lane];
    float bnh_lo = bhh_c[128+lane],  bnh_hi = bhh_c[160+lane];
    #pragma unroll
    for (int i=0;i<4;i++){
        int rl = r0+i;
        float ho_lo = hds[rl*68 + lane];
        float ho_hi = hds[rl*68 + 32 + lane];
        float r_lo = sigm(aR[i].x + brc_lo);
        float r_hi = sigm(aR[i].y + brc_hi);
        float z_lo = sigm(aZ[i].x + bzc_lo);
        float z_hi = sigm(aZ[i].y + bzc_hi);
        float n_lo = tanh_(aI[i].x + bni_lo + r_lo*(aH[i].x + bnh_lo));
        float n_hi = tanh_(aI[i].y + bni_hi + r_hi*(aH[i].y + bnh_hi));
        out[(rbase+rl)*64 + lane]      = (1.0f - z_lo)*n_lo + z_lo*ho_lo;
        out[(rbase+rl)*64 + 32 + lane] = (1.0f - z_hi)*n_hi + z_hi*ho_hi;
    }
}

// =====================================================================
extern "C" void kernel_launch(void* const* d_in, const int* in_sizes, int n_in,
                              void* d_out, int out_size)
{
    (void)in_sizes; (void)n_in; (void)out_size;
    const float* obs    = (const float*)d_in[0];
    const float* hidden = (const float*)d_in[1];
    const float* gum    = (const float*)d_in[2];
    const float* W_enc  = (const float*)d_in[3];
    const float* b_enc  = (const float*)d_in[4];
    const float* Wih_f  = (const float*)d_in[5];
    const float* Whh_f  = (const float*)d_in[6];
    const float* bih_f  = (const float*)d_in[7];
    const float* bhh_f  = (const float*)d_in[8];
    const float* Wih_b  = (const float*)d_in[9];
    const float* Whh_b  = (const float*)d_in[10];
    const float* bih_b  = (const float*)d_in[11];
    const float* bhh_b  = (const float*)d_in[12];
    const float* W_hard = (const float*)d_in[13];
    const float* b_hard = (const float*)d_in[14];
    const float* Wq     = (const float*)d_in[15];
    const float* Wk     = (const float*)d_in[16];
    const float* Wv     = (const float*)d_in[17];
    const float* b_v    = (const float*)d_in[18];
    const float* Wih_c  = (const float*)d_in[19];
    const float* Whh_c  = (const float*)d_in[20];
    const float* bih_c  = (const float*)d_in[21];
    const float* bhh_c  = (const float*)d_in[22];
    float* out = (float*)d_out;

    const int sm0 = (64*68 + 4096) * (int)sizeof(float);      // 33,792 B
    const int sm2 = 6400 * (int)sizeof(u64t);                 // 51,200 B
    const int sm4 = (5*64*68 + 2*64*16) * (int)sizeof(float); // 95,232 B

    cudaFuncSetAttribute(k_enc,       cudaFuncAttributeMaxDynamicSharedMemorySize, sm0);
    cudaFuncSetAttribute(k_gru_mma,   cudaFuncAttributeMaxDynamicSharedMemorySize, sm2);
    cudaFuncSetAttribute(k_attn_cell, cudaFuncAttributeMaxDynamicSharedMemorySize, sm4);

    k_enc<<<256, 256, sm0>>>(obs, W_enc, b_enc);
    k_packW<<<24, 256>>>(Wih_c, Whh_c);
    k_packP<<<120, 256>>>(Wq, Wk, Wv, b_v, Wih_f, Wih_b,
                          bih_f, bhh_f, bih_b, bhh_b);
    k_proj_mma<<<dim3(256,5), 128>>>();
    k_gru_mma<<<512, 128, sm2>>>(Whh_f, Whh_b, bhh_f, bhh_b, W_hard);
    k_attn_cell<<<256, 512, sm4>>>(hidden, gum, b_hard, bih_c, bhh_c, out);
}

// round 17
// speedup vs baseline: 1.6016x; 1.1057x over previous
#include <cuda_runtime.h>
#include <cuda_bf16.h>
#include <cuda_fp16.h>
#include <math.h>
#include <stdint.h>

#define NROWS 16384
#define Tt 15
#define EPSg 1e-10f

typedef unsigned long long u64t;

// ---------------- scratch ----------------
__device__ float g_h[NROWS*64];
__device__ float g_q[NROWS*64];
__device__ float g_k[NROWS*64];
__device__ float g_v[NROWS*64];
// PLAIN layout: [row][gate*64+c]; Cb has bih (+bhh for r,z) folded
__device__ float g_Gf [NROWS*192];
__device__ float g_Cbf[NROWS*192];
__device__ float g_Gb [NROWS*192];
__device__ float g_Cbb[NROWS*192];
__device__ float g_lf[NROWS*2*Tt];
__device__ float g_lb[NROWS*2*Tt];
__device__ float g_Wc[64*3*32*4];
// projection B fragments (single fp16) [kt4][jn120][lane32] + folded bias
__device__ u64t  g_Wp[4*120*32];
__device__ float g_Bb[960];

__device__ __forceinline__ float sigm(float x){ return 1.0f/(1.0f+__expf(-x)); }
__device__ __forceinline__ float tanh_(float x){ return 2.0f/(1.0f+__expf(-2.0f*x)) - 1.0f; }

__device__ __forceinline__ u64t pk(float x, float y){
    u64t r; asm("mov.b64 %0,{%1,%2};" : "=l"(r) : "f"(x), "f"(y)); return r;
}
__device__ __forceinline__ float2 up(u64t v){
    float2 r; asm("mov.b64 {%0,%1},%2;" : "=f"(r.x), "=f"(r.y) : "l"(v)); return r;
}
__device__ __forceinline__ void fma2(u64t& d, u64t a, u64t b){
    asm("fma.rn.f32x2 %0,%1,%2,%0;" : "+l"(d) : "l"(a), "l"(b));
}
__device__ __forceinline__ int pairpos64(int d, int c){
    return ((d<<5) + (((c>>5)&1)<<4) + (c&15))*2 + ((c>>4)&1);
}
// fp16 pack helpers
__device__ __forceinline__ uint32_t h2pair(float a, float b){
    __half2 t = __floats2half2_rn(a, b);
    return *(uint32_t*)&t;
}
__device__ __forceinline__ float h16hi(float x){
    return __half2float(__float2half_rn(x));
}
__device__ __forceinline__ float2 h22f(uint32_t u){
    __half2 h = *(__half2*)&u;
    return __half22float2(h);
}
__device__ __forceinline__ void mma16816h(float* d, uint32_t a0, uint32_t a1,
                                          uint32_t a2, uint32_t a3,
                                          uint32_t b0, uint32_t b1){
    asm volatile(
      "mma.sync.aligned.m16n8k16.row.col.f32.f16.f16.f32 "
      "{%0,%1,%2,%3},{%4,%5,%6,%7},{%8,%9},{%0,%1,%2,%3};"
      : "+f"(d[0]), "+f"(d[1]), "+f"(d[2]), "+f"(d[3])
      : "r"(a0), "r"(a1), "r"(a2), "r"(a3), "r"(b0), "r"(b1));
}

// =====================================================================
// K0: encoder (unchanged)
// =====================================================================
__global__ __launch_bounds__(256)
void k_enc(const float* __restrict__ obs,
           const float* __restrict__ W_enc, const float* __restrict__ b_enc)
{
    extern __shared__ float sm[];
    float* Os = sm;
    float* Wt = sm + 64*68;
    const u64t* Wt64 = (const u64t*)Wt;
    const int tid = threadIdx.x;
    const int rbase = blockIdx.x * 64;
    const int ty = tid >> 4, tx = tid & 15;
    const int r0 = ty * 4;
    int dcol[4];
    #pragma unroll
    for (int k=0;k<4;k++) dcol[k] = tx + ((k>>1)<<5) + ((k&1)<<4);

    for (int idx = tid; idx < 4096; idx += 256) {
        int r = idx >> 6, c = idx & 63;
        Os[r*68+c] = obs[(rbase+r)*64 + c];
        Wt[pairpos64(r, c)] = W_enc[idx];
    }
    __syncthreads();

    u64t acc[4][2];
    #pragma unroll
    for (int i=0;i<4;i++){ acc[i][0]=0ull; acc[i][1]=0ull; }
    for (int dd=0; dd<64; ++dd){
        u64t pa[4];
        #pragma unroll
        for (int i=0;i<4;i++){ float a=Os[(r0+i)*68+dd]; pa[i]=pk(a,a); }
        #pragma unroll
        for (int p=0;p<2;p++){
            u64t w = Wt64[dd*32 + p*16 + tx];
            #pragma unroll
            for (int i=0;i<4;i++) fma2(acc[i][p], pa[i], w);
        }
    }
    #pragma unroll
    for (int i=0;i<4;i++)
        #pragma unroll
        for (int p=0;p<2;p++){
            float2 v = up(acc[i][p]);
            int d0 = dcol[2*p], d1 = dcol[2*p+1];
            g_h[(rbase+r0+i)*64 + d0] = fmaxf(v.x + b_enc[d0], 0.0f);
            g_h[(rbase+r0+i)*64 + d1] = fmaxf(v.y + b_enc[d1], 0.0f);
        }
}

// =====================================================================
// K0b: pack cell weights (unchanged)
// =====================================================================
__global__ __launch_bounds__(256)
void k_packW(const float* __restrict__ Wih_c, const float* __restrict__ Whh_c)
{
    int idx = blockIdx.x * 256 + threadIdx.x;
    if (idx >= 6144) return;
    int dd = idx / 96;
    int rem = idx - dd*96;
    int gate = rem >> 5;
    int c = rem & 31;
    float4 w;
    w.x = Wih_c[(gate*64 + c     )*64 + dd];
    w.y = Wih_c[(gate*64 + c + 32)*64 + dd];
    w.z = Whh_c[(gate*64 + c     )*64 + dd];
    w.w = Whh_c[(gate*64 + c + 32)*64 + dd];
    ((float4*)g_Wc)[idx] = w;
}

// =====================================================================
// K0c: pack projection weights (single fp16 fragments)
// =====================================================================
__device__ __forceinline__ float projW(int k, int m,
    const float* Wq, const float* Wk, const float* Wv,
    const float* Wih_f, const float* Wih_b)
{
    if (m < 192){
        const float* W = (m<64) ? Wq : (m<128 ? Wk : Wv);
        return W[k*64 + (m & 63)];
    }
    if (m < 384) return Wih_f[(m-192)*128 + k];
    if (m < 576) return Wih_f[(m-384)*128 + 64 + k];
    if (m < 768) return Wih_b[(m-576)*128 + k];
    return Wih_b[(m-768)*128 + 64 + k];
}

__global__ __launch_bounds__(256)
void k_packP(const float* __restrict__ Wq, const float* __restrict__ Wk,
             const float* __restrict__ Wv, const float* __restrict__ b_v,
             const float* __restrict__ Wih_f, const float* __restrict__ Wih_b,
             const float* __restrict__ bih_f, const float* __restrict__ bhh_f,
             const float* __restrict__ bih_b, const float* __restrict__ bhh_b)
{
    int idx = blockIdx.x * 256 + threadIdx.x;   // 15360 frag slots
    if (idx < 15360){
        int lane = idx & 31, f = idx >> 5;
        int jn = f % 120, kt = f / 120;
        int gg = lane >> 2, tt = lane & 3;
        int m = 8*jn + gg;
        int k0 = 16*kt + 2*tt;
        float w0 = projW(k0,   m, Wq,Wk,Wv,Wih_f,Wih_b);
        float w1 = projW(k0+1, m, Wq,Wk,Wv,Wih_f,Wih_b);
        float w2 = projW(k0+8, m, Wq,Wk,Wv,Wih_f,Wih_b);
        float w3 = projW(k0+9, m, Wq,Wk,Wv,Wih_f,Wih_b);
        g_Wp[idx] = ((u64t)h2pair(w2,w3) << 32) | (u64t)h2pair(w0,w1);
    }
    if (idx < 960){
        int m = idx;
        float b = 0.f;
        if (m >= 128 && m < 192) b = b_v[m-128];
        else if (m >= 192 && m < 384){
            int ml = m-192; b = bih_f[ml] + (ml < 128 ? bhh_f[ml] : 0.f);
        } else if (m >= 576 && m < 768){
            int ml = m-576; b = bih_b[ml] + (ml < 128 ? bhh_b[ml] : 0.f);
        }
        g_Bb[m] = b;
    }
}

// =====================================================================
// K1: projections, fp16 2-term (A split, B single). grid (256,5).
// =====================================================================
__global__ __launch_bounds__(128)
void k_proj_mma()
{
    const int tid = threadIdx.x;
    const int w = tid >> 5, lane = tid & 31;
    const int g = lane >> 2, tg = lane & 3;
    const int rowbase = blockIdx.x * 64 + w*16;
    const int rg0 = rowbase + g, rg8 = rg0 + 8;
    const int jn0 = blockIdx.y * 24;

    uint32_t Ahi[4][4], Alo[4][4];
    #pragma unroll
    for (int kt=0; kt<4; ++kt){
        float2 x0 = *(const float2*)&g_h[(size_t)rg0*64 + 16*kt + 2*tg];
        float2 x1 = *(const float2*)&g_h[(size_t)rg8*64 + 16*kt + 2*tg];
        float2 x2 = *(const float2*)&g_h[(size_t)rg0*64 + 16*kt + 8 + 2*tg];
        float2 x3 = *(const float2*)&g_h[(size_t)rg8*64 + 16*kt + 8 + 2*tg];
        Ahi[kt][0] = h2pair(x0.x, x0.y);
        Alo[kt][0] = h2pair(x0.x - h16hi(x0.x), x0.y - h16hi(x0.y));
        Ahi[kt][1] = h2pair(x1.x, x1.y);
        Alo[kt][1] = h2pair(x1.x - h16hi(x1.x), x1.y - h16hi(x1.y));
        Ahi[kt][2] = h2pair(x2.x, x2.y);
        Alo[kt][2] = h2pair(x2.x - h16hi(x2.x), x2.y - h16hi(x2.y));
        Ahi[kt][3] = h2pair(x3.x, x3.y);
        Alo[kt][3] = h2pair(x3.x - h16hi(x3.x), x3.y - h16hi(x3.y));
    }

    const u64t* Wp = g_Wp + lane;

    #pragma unroll 4
    for (int jj = 0; jj < 24; ++jj){
        const int jn = jn0 + jj;
        float D[4] = {0.f, 0.f, 0.f, 0.f};
        #pragma unroll
        for (int kt=0; kt<4; ++kt){
            u64t bh = Wp[(kt*120 + jn)*32];
            uint32_t bh0 = (uint32_t)bh, bh1 = (uint32_t)(bh>>32);
            mma16816h(D, Ahi[kt][0],Ahi[kt][1],Ahi[kt][2],Ahi[kt][3], bh0,bh1);
            mma16816h(D, Alo[kt][0],Alo[kt][1],Alo[kt][2],Alo[kt][3], bh0,bh1);
        }
        float2 bb = *(const float2*)&g_Bb[8*jn + 2*tg];
        D[0] += bb.x; D[1] += bb.y; D[2] += bb.x; D[3] += bb.y;
        if (jn >= 16 && jn < 24){
            D[0]=fmaxf(D[0],0.f); D[1]=fmaxf(D[1],0.f);
            D[2]=fmaxf(D[2],0.f); D[3]=fmaxf(D[3],0.f);
        }
        float* dst; int stride, col0;
        if (jn < 8)        { dst = g_q;   stride = 64;  col0 = 8*jn; }
        else if (jn < 16)  { dst = g_k;   stride = 64;  col0 = 8*jn - 64; }
        else if (jn < 24)  { dst = g_v;   stride = 64;  col0 = 8*jn - 128; }
        else {
            int s2 = (jn - 24) / 24;
            col0 = 8*((jn - 24) % 24);
            dst = (s2==0) ? g_Cbf : (s2==1) ? g_Gf : (s2==2) ? g_Cbb : g_Gb;
            stride = 192;
        }
        *(float2*)&dst[(size_t)rg0*stride + col0 + 2*tg] = make_float2(D[0], D[1]);
        *(float2*)&dst[(size_t)rg8*stride + col0 + 2*tg] = make_float2(D[2], D[3]);
    }
}

// =====================================================================
// K2: GRU, fp16 2-term split (A = hi+lo fp16, B single fp16).
// R12 schedule: grid 512, block 128, 2 CTAs/SM, warp owns 16 rows.
// smem: B fragments [kt4][jn25][lane32] u64 = 25.6KB
// =====================================================================
__global__ __launch_bounds__(128,2)
void k_gru_mma(const float* __restrict__ Whh_f, const float* __restrict__ Whh_b,
               const float* __restrict__ bhh_f, const float* __restrict__ bhh_b,
               const float* __restrict__ W_hard)
{
    extern __shared__ u64t Bsm[];   // 3200 u64
    const int tid = threadIdx.x;
    const int w = tid >> 5, lane = tid & 31;
    const int g = lane >> 2, tg = lane & 3;
    const int fwd = (blockIdx.x < 256);
    const int rbase = (blockIdx.x & 255) * 64;
    const float* Whh = fwd ? Whh_f : Whh_b;
    const float* bhh = fwd ? bhh_f : bhh_b;
    const float* Gg  = fwd ? g_Gf  : g_Gb;
    const float* Cbg = fwd ? g_Cbf : g_Cbb;
    u64t* lout = (u64t*)(fwd ? g_lf : g_lb);
    const int whb = fwd ? 0 : 64;

    for (int idx = tid; idx < 3200; idx += 128){
        int ln = idx & 31, f = idx >> 5;
        int kt = f / 25, jn = f - kt*25;
        int gg = ln >> 2, tt = ln & 3;
        float w0,w1,w2,w3;
        if (jn < 24){
            const float* src = Whh + (8*jn + gg)*64 + 16*kt;
            w0 = src[2*tt]; w1 = src[2*tt+1]; w2 = src[8+2*tt]; w3 = src[9+2*tt];
        } else if (gg < 2){
            int kb = whb + 16*kt;
            w0 = W_hard[(kb+2*tt  )*2 + gg];
            w1 = W_hard[(kb+2*tt+1)*2 + gg];
            w2 = W_hard[(kb+8+2*tt  )*2 + gg];
            w3 = W_hard[(kb+9+2*tt  )*2 + gg];
        } else { w0=w1=w2=w3=0.f; }
        Bsm[idx] = ((u64t)h2pair(w2,w3) << 32) | (u64t)h2pair(w0,w1);
    }
    __syncthreads();

    const int rowbase = rbase + w*16;
    const int rg0 = rowbase + g, rg8 = rg0 + 8;
    const float* cb0p = Cbg + (size_t)rg0*192 + 2*tg;
    const float* cb8p = Cbg + (size_t)rg8*192 + 2*tg;
    const float* Gbase = Gg + (size_t)rowbase*192 + 2*tg;
    const u64t* Bw = Bsm + lane;

    float bnv[8][2];
    #pragma unroll
    for (int j=0;j<8;j++){
        float2 v = *(const float2*)&bhh[128 + 8*j + 2*tg];
        bnv[j][0] = v.x; bnv[j][1] = v.y;
    }

    float D[25][4];
    uint32_t Ahi[4][4], Alo[4][4];
    #pragma unroll
    for (int kt=0;kt<4;kt++)
        #pragma unroll
        for (int x=0;x<4;x++){ Ahi[kt][x]=0u; Alo[kt][x]=0u; }

    #pragma unroll 1
    for (int ti = 0; ti < Tt; ++ti){
        const int t = fwd ? ti : (Tt-1-ti);
        const int jl0 = t + (t >= g);
        const int jl8 = t + (t >= g+8);
        const float* g0p = Gbase + jl0*192;
        const float* g8p = Gbase + jl8*192;

        #pragma unroll
        for (int jj=0; jj<16; ++jj){
            float2 c0 = *(const float2*)(cb0p + 8*jj);
            float2 e0 = *(const float2*)(g0p  + 8*jj);
            float2 c8 = *(const float2*)(cb8p + 8*jj);
            float2 e8 = *(const float2*)(g8p  + 8*jj);
            D[jj][0] = c0.x + e0.x; D[jj][1] = c0.y + e0.y;
            D[jj][2] = c8.x + e8.x; D[jj][3] = c8.y + e8.y;
        }
        #pragma unroll
        for (int j=0;j<8;j++){
            D[16+j][0] = bnv[j][0]; D[16+j][1] = bnv[j][1];
            D[16+j][2] = bnv[j][0]; D[16+j][3] = bnv[j][1];
        }
        D[24][0]=0.f; D[24][1]=0.f; D[24][2]=0.f; D[24][3]=0.f;

        if (ti){
            #pragma unroll
            for (int jn=0; jn<25; ++jn){
                #pragma unroll
                for (int kt=0; kt<4; ++kt){
                    u64t bh = Bw[(kt*25 + jn)*32];
                    uint32_t bh0 = (uint32_t)bh, bh1 = (uint32_t)(bh>>32);
                    mma16816h(D[jn], Ahi[kt][0],Ahi[kt][1],Ahi[kt][2],Ahi[kt][3], bh0,bh1);
                    mma16816h(D[jn], Alo[kt][0],Alo[kt][1],Alo[kt][2],Alo[kt][3], bh0,bh1);
                }
            }
            if (tg == 0){
                int tp = fwd ? (ti-1) : (Tt-ti);
                lout[(size_t)rg0*Tt + tp] = pk(D[24][0], D[24][1]);
                lout[(size_t)rg8*Tt + tp] = pk(D[24][2], D[24][3]);
            }
        }

        #pragma unroll
        for (int j=0;j<8;++j){
            float2 cn0 = *(const float2*)(cb0p + 128 + 8*j);
            float2 en0 = *(const float2*)(g0p  + 128 + 8*j);
            float2 cn8 = *(const float2*)(cb8p + 128 + 8*j);
            float2 en8 = *(const float2*)(g8p  + 128 + 8*j);
            int kt = j >> 1, px = (j & 1) * 2;
            float2 hA = h22f(Ahi[kt][px]),   lA = h22f(Alo[kt][px]);
            float2 hB = h22f(Ahi[kt][px+1]), lB = h22f(Alo[kt][px+1]);
            float ho0 = hA.x + lA.x, ho1 = hA.y + lA.y;
            float ho2 = hB.x + lB.x, ho3 = hB.y + lB.y;
            float r0 = sigm(D[j][0]),  r1 = sigm(D[j][1]);
            float r2 = sigm(D[j][2]),  r3 = sigm(D[j][3]);
            float z0 = sigm(D[j+8][0]), z1 = sigm(D[j+8][1]);
            float z2 = sigm(D[j+8][2]), z3 = sigm(D[j+8][3]);
            float n0 = tanh_(cn0.x + en0.x + r0*D[j+16][0]);
            float n1 = tanh_(cn0.y + en0.y + r1*D[j+16][1]);
            float n2 = tanh_(cn8.x + en8.x + r2*D[j+16][2]);
            float n3 = tanh_(cn8.y + en8.y + r3*D[j+16][3]);
            float h0 = (1.f - z0)*n0 + z0*ho0;
            float h1 = (1.f - z1)*n1 + z1*ho1;
            float h2 = (1.f - z2)*n2 + z2*ho2;
            float h3 = (1.f - z3)*n3 + z3*ho3;
            Ahi[kt][px]   = h2pair(h0, h1);
            Alo[kt][px]   = h2pair(h0 - h16hi(h0), h1 - h16hi(h1));
            Ahi[kt][px+1] = h2pair(h2, h3);
            Alo[kt][px+1] = h2pair(h2 - h16hi(h2), h3 - h16hi(h3));
        }
    }

    {
        float dl[4] = {0.f,0.f,0.f,0.f};
        #pragma unroll
        for (int kt=0; kt<4; ++kt){
            u64t bh = Bw[(kt*25 + 24)*32];
            uint32_t bh0 = (uint32_t)bh, bh1 = (uint32_t)(bh>>32);
            mma16816h(dl, Ahi[kt][0],Ahi[kt][1],Ahi[kt][2],Ahi[kt][3], bh0,bh1);
            mma16816h(dl, Alo[kt][0],Alo[kt][1],Alo[kt][2],Alo[kt][3], bh0,bh1);
        }
        if (tg == 0){
            int tp = fwd ? (Tt-1) : 0;
            lout[(size_t)rg0*Tt + tp] = pk(dl[0], dl[1]);
            lout[(size_t)rg8*Tt + tp] = pk(dl[2], dl[3]);
        }
    }
}

// =====================================================================
// K3: gumbel + attention + final GRU cell (unchanged)
// =====================================================================
__global__ __launch_bounds__(512,2)
void k_attn_cell(const float* __restrict__ hidden,
                 const float* __restrict__ gum,
                 const float* __restrict__ b_hard,
                 const float* __restrict__ bih_c, const float* __restrict__ bhh_c,
                 float* __restrict__ out)
{
    extern __shared__ float sm[];
    float* qs  = sm;
    float* ks_ = qs  + 64*68;
    float* vs  = ks_ + 64*68;
    float* hds = vs  + 64*68;
    float* xs  = hds + 64*68;
    float* hw  = xs  + 64*68;
    float* sc  = hw  + 64*16;
    const int tid = threadIdx.x;
    const int rbase = blockIdx.x * 64;

    for (int idx=tid; idx<1024; idx+=512){
        int r=idx>>4, c4=idx&15;
        ((float4*)qs )[r*17+c4] = ((const float4*)g_q)[(rbase+r)*16+c4];
        ((float4*)ks_)[r*17+c4] = ((const float4*)g_k)[(rbase+r)*16+c4];
        ((float4*)vs )[r*17+c4] = ((const float4*)g_v)[(rbase+r)*16+c4];
        ((float4*)hds)[r*17+c4] = ((const float4*)hidden)[(rbase+r)*16+c4];
    }
    {
        const float bh0 = b_hard[0], bh1 = b_hard[1];
        for (int idx=tid; idx<64*Tt; idx+=512){
            int r=idx/Tt, t=idx-r*Tt;
            int row = rbase + r;
            float L0 = g_lf[row*(2*Tt)+2*t]   + g_lb[row*(2*Tt)+2*t]   + bh0;
            float L1 = g_lf[row*(2*Tt)+2*t+1] + g_lb[row*(2*Tt)+2*t+1] + bh1;
            int gi = (row*Tt + t)*2;
            float u0 = gum[gi], u1 = gum[gi+1];
            float gg0 = -logf(-logf(u0+EPSg)+EPSg);
            float gg1 = -logf(-logf(u1+EPSg)+EPSg);
            float dlt = ((L1+gg1)-(L0+gg0)) * 100.0f;
            hw[r*16+t] = 1.0f/(1.0f+__expf(-dlt));
        }
    }
    __syncthreads();

    {
        int rp = tid>>3, qq = tid&7;
        #pragma unroll
        for (int s2=0; s2<2; ++s2){
            int t = qq + 8*s2;
            if (t < Tt){
                int ii = rp & 15;
                int jl = (rp & 48) + t + (t>=ii ? 1 : 0);
                float dot=0.f;
                #pragma unroll 8
                for (int d=0; d<64; ++d) dot += qs[rp*68+d]*ks_[jl*68+d];
                sc[rp*16+t] = dot*0.125f;
            }
        }
    }
    __syncthreads();
    if (tid < 64){
        int r=tid;
        float m=-1e30f;
        #pragma unroll
        for (int t=0;t<Tt;t++) m = fmaxf(m, sc[r*16+t]);
        float e[Tt]; float ssum=0.f;
        #pragma unroll
        for (int t=0;t<Tt;t++){ e[t]=__expf(sc[r*16+t]-m); ssum+=e[t]; }
        float inv = 1.0f/ssum;
        #pragma unroll
        for (int t=0;t<Tt;t++) sc[r*16+t] = e[t]*inv*hw[r*16+t];
    }
    __syncthreads();
    for (int idx=tid; idx<4096; idx+=512){
        int r=idx>>6, d=idx&63;
        int ii = r & 15, rb2 = r & 48;
        float x=0.f;
        #pragma unroll
        for (int t=0;t<Tt;t++){
            int jl = rb2 + t + (t>=ii ? 1 : 0);
            x += vs[jl*68+d]*sc[r*16+t];
        }
        xs[r*68+d]=x;
    }
    __syncthreads();

    const int wid = tid >> 5, lane = tid & 31;
    const int r0 = wid * 4;
    const float4* Wc4 = (const float4*)g_Wc;

    float2 aR[4], aZ[4], aI[4], aH[4];
    #pragma unroll
    for (int i=0;i<4;i++){
        aR[i]=make_float2(0.f,0.f); aZ[i]=make_float2(0.f,0.f);
        aI[i]=make_float2(0.f,0.f); aH[i]=make_float2(0.f,0.f);
    }
    #pragma unroll 2
    for (int dd=0; dd<64; ++dd){
        float4 w0 = Wc4[(dd*3+0)*32 + lane];
        float4 w1 = Wc4[(dd*3+1)*32 + lane];
        float4 w2 = Wc4[(dd*3+2)*32 + lane];
        #pragma unroll
        for (int i=0;i<4;i++){
            float x = xs [(r0+i)*68 + dd];
            float h = hds[(r0+i)*68 + dd];
            aR[i].x += x*w0.x + h*w0.z;  aR[i].y += x*w0.y + h*w0.w;
            aZ[i].x += x*w1.x + h*w1.z;  aZ[i].y += x*w1.y + h*w1.w;
            aI[i].x += x*w2.x;           aI[i].y += x*w2.y;
            aH[i].x += h*w2.z;           aH[i].y += h*w2.w;
        }
    }
    float brc_lo = bih_c[lane]      + bhh_c[lane];
    float brc_hi = bih_c[lane+32]   + bhh_c[lane+32];
    float bzc_lo = bih_c[64+lane]   + bhh_c[64+lane];
    float bzc_hi = bih_c[96+lane]   + bhh_c[96+lane];
    float bni_lo = bih_c[128+lane],  bni_hi = bih_c[160+lane];
    float bnh_lo = bhh_c[128+lane],  bnh_hi = bhh_c[160+lane];
    #pragma unroll
    for (int i=0;i<4;i++){
        int rl = r0+i;
        float ho_lo = hds[rl*68 + lane];
        float ho_hi = hds[rl*68 + 32 + lane];
        float r_lo = sigm(aR[i].x + brc_lo);
        float r_hi = sigm(aR[i].y + brc_hi);
        float z_lo = sigm(aZ[i].x + bzc_lo);
        float z_hi = sigm(aZ[i].y + bzc_hi);
        float n_lo = tanh_(aI[i].x + bni_lo + r_lo*(aH[i].x + bnh_lo));
        float n_hi = tanh_(aI[i].y + bni_hi + r_hi*(aH[i].y + bnh_hi));
        out[(rbase+rl)*64 + lane]      = (1.0f - z_lo)*n_lo + z_lo*ho_lo;
        out[(rbase+rl)*64 + 32 + lane] = (1.0f - z_hi)*n_hi + z_hi*ho_hi;
    }
}

// =====================================================================
extern "C" void kernel_launch(void* const* d_in, const int* in_sizes, int n_in,
                              void* d_out, int out_size)
{
    (void)in_sizes; (void)n_in; (void)out_size;
    const float* obs    = (const float*)d_in[0];
    const float* hidden = (const float*)d_in[1];
    const float* gum    = (const float*)d_in[2];
    const float* W_enc  = (const float*)d_in[3];
    const float* b_enc  = (const float*)d_in[4];
    const float* Wih_f  = (const float*)d_in[5];
    const float* Whh_f  = (const float*)d_in[6];
    const float* bih_f  = (const float*)d_in[7];
    const float* bhh_f  = (const float*)d_in[8];
    const float* Wih_b  = (const float*)d_in[9];
    const float* Whh_b  = (const float*)d_in[10];
    const float* bih_b  = (const float*)d_in[11];
    const float* bhh_b  = (const float*)d_in[12];
    const float* W_hard = (const float*)d_in[13];
    const float* b_hard = (const float*)d_in[14];
    const float* Wq     = (const float*)d_in[15];
    const float* Wk     = (const float*)d_in[16];
    const float* Wv     = (const float*)d_in[17];
    const float* b_v    = (const float*)d_in[18];
    const float* Wih_c  = (const float*)d_in[19];
    const float* Whh_c  = (const float*)d_in[20];
    const float* bih_c  = (const float*)d_in[21];
    const float* bhh_c  = (const float*)d_in[22];
    float* out = (float*)d_out;

    const int sm0 = (64*68 + 4096) * (int)sizeof(float);      // 33,792 B
    const int sm2 = 3200 * (int)sizeof(u64t);                 // 25,600 B
    const int sm4 = (5*64*68 + 2*64*16) * (int)sizeof(float); // 95,232 B

    cudaFuncSetAttribute(k_enc,       cudaFuncAttributeMaxDynamicSharedMemorySize, sm0);
    cudaFuncSetAttribute(k_gru_mma,   cudaFuncAttributeMaxDynamicSharedMemorySize, sm2);
    cudaFuncSetAttribute(k_attn_cell, cudaFuncAttributeMaxDynamicSharedMemorySize, sm4);

    k_enc<<<256, 256, sm0>>>(obs, W_enc, b_enc);
    k_packW<<<24, 256>>>(Wih_c, Whh_c);
    k_packP<<<60, 256>>>(Wq, Wk, Wv, b_v, Wih_f, Wih_b,
                         bih_f, bhh_f, bih_b, bhh_b);
    k_proj_mma<<<dim3(256,5), 128>>>();
    k_gru_mma<<<512, 128, sm2>>>(Whh_f, Whh_b, bhh_f, bhh_b, W_hard);
    k_attn_cell<<<256, 512, sm4>>>(hidden, gum, b_hard, bih_c, bhh_c, out);
}